// round 5
// baseline (speedup 1.0000x reference)
#include <cuda_runtime.h>
#include <cuda_bf16.h>
#include <math.h>
#include <stdint.h>

#define N_ 50000
#define D_ 256
#define E_ 250000
#define T_ 6
#define H_ 4
#define K_ 64

// ---------------- scratch (device globals; no runtime allocation) ----------
__device__ float g_hs1[(size_t)N_ * D_];
__device__ float g_hd1[(size_t)N_ * D_];
__device__ float g_hs2[(size_t)N_ * D_];
__device__ float g_hd2[(size_t)N_ * D_];
__device__ float g_h1[(size_t)N_ * D_];
__device__ float g_h2[(size_t)N_ * D_];
__device__ float g_p[(size_t)E_ * H_];
__device__ float g_den[(size_t)N_ * H_];
__device__ float g_pool[(size_t)K_ * D_];
__device__ float g_esum[T_];

// ---------------- helpers ---------------------------------------------------
__device__ __forceinline__ void redAddV4(float* p, float a, float b, float c, float d) {
    asm volatile("red.global.add.v4.f32 [%0], {%1,%2,%3,%4};"
                 :: "l"(p), "f"(a), "f"(b), "f"(c), "f"(d) : "memory");
}
__device__ __forceinline__ void redAddV2(float* p, float a, float b) {
    asm volatile("red.global.add.v2.f32 [%0], {%1,%2};"
                 :: "l"(p), "f"(a), "f"(b) : "memory");
}

__device__ __forceinline__ uint32_t smem_u32(const void* p) {
    return (uint32_t)__cvta_generic_to_shared(p);
}

#define LDSM4(R0, R1, R2, R3, ADDR) \
    asm volatile("ldmatrix.sync.aligned.m8n8.x4.shared.b16 {%0,%1,%2,%3}, [%4];" \
                 : "=r"(R0), "=r"(R1), "=r"(R2), "=r"(R3) : "r"(ADDR))

#define LDSM4T(R0, R1, R2, R3, ADDR) \
    asm volatile("ldmatrix.sync.aligned.m8n8.x4.trans.shared.b16 {%0,%1,%2,%3}, [%4];" \
                 : "=r"(R0), "=r"(R1), "=r"(R2), "=r"(R3) : "r"(ADDR))

__device__ __forceinline__ void mma_bf16(float* c, const uint32_t* a, const uint32_t* b) {
    asm volatile("mma.sync.aligned.m16n8k16.row.col.f32.bf16.bf16.f32 "
                 "{%0,%1,%2,%3},{%4,%5,%6,%7},{%8,%9},{%0,%1,%2,%3};"
                 : "+f"(c[0]), "+f"(c[1]), "+f"(c[2]), "+f"(c[3])
                 : "r"(a[0]), "r"(a[1]), "r"(a[2]), "r"(a[3]), "r"(b[0]), "r"(b[1]));
}

__device__ __forceinline__ void split1(float x, unsigned short* hi, unsigned short* lo) {
    __nv_bfloat16 h = __float2bfloat16(x);
    *hi = __bfloat16_as_ushort(h);
    float r = x - __bfloat162float(h);
    *lo = __bfloat16_as_ushort(__float2bfloat16(r));
}

__device__ __forceinline__ uint32_t pack_bf2(float a, float b) {
    __nv_bfloat16 ha = __float2bfloat16(a);
    __nv_bfloat16 hb = __float2bfloat16(b);
    return (uint32_t)__bfloat16_as_ushort(ha) | ((uint32_t)__bfloat16_as_ushort(hb) << 16);
}
__device__ __forceinline__ uint32_t pack_bf2_lo(float a, float b) {
    __nv_bfloat16 ha = __float2bfloat16(a);
    __nv_bfloat16 hb = __float2bfloat16(b);
    float ra = a - __bfloat162float(ha);
    float rb = b - __bfloat162float(hb);
    __nv_bfloat16 la = __float2bfloat16(ra);
    __nv_bfloat16 lb = __float2bfloat16(rb);
    return (uint32_t)__bfloat16_as_ushort(la) | ((uint32_t)__bfloat16_as_ushort(lb) << 16);
}

// ---------------- init kernels ----------------------------------------------
__global__ void init1_kernel() {
    int i = blockIdx.x * blockDim.x + threadIdx.x;
    int st = gridDim.x * blockDim.x;
    for (int j = i; j < N_ * D_; j += st) g_h1[j] = 0.0f;
    for (int j = i; j < N_ * H_; j += st) g_den[j] = 0.0f;
    for (int j = i; j < K_ * D_; j += st) g_pool[j] = 0.0f;
    for (int j = i; j < T_; j += st) g_esum[j] = 0.0f;
}

__global__ void init2_kernel() {
    int i = blockIdx.x * blockDim.x + threadIdx.x;
    int st = gridDim.x * blockDim.x;
    for (int j = i; j < N_ * D_; j += st) g_h2[j] = 0.0f;
    for (int j = i; j < N_ * H_; j += st) g_den[j] = 0.0f;
}

// =============== shared GEMM mainloop body (round-2 form, no prefetch) =======
// C[M x 256] = f(A)[M x 256] @ B[256 x 256]
// mode 0: f(A) = A * nm[row]; mode 1: f(A) = relu(A)
struct GemmSmem {
    unsigned short Ahi[128 * 40];
    unsigned short Alo[128 * 40];
    unsigned short Bhi[32 * 136];
    unsigned short Blo[32 * 136];
};

__device__ __forceinline__ void gemm_body(
    GemmSmem& sm, const float* __restrict__ A, const float* __restrict__ nm,
    const float* __restrict__ B, float* __restrict__ C, int M, int mode,
    int bm, int bn)
{
    constexpr int ASTR = 40;
    constexpr int BSTR = 136;
    const int tid = threadIdx.x;
    const int lane = tid & 31;
    const int warp = tid >> 5;
    const int wm = (warp & 1) * 64;
    const int wn = (warp >> 1) * 32;

    float acc[4][4][4];
#pragma unroll
    for (int i = 0; i < 4; i++)
#pragma unroll
        for (int j = 0; j < 4; j++)
#pragma unroll
            for (int r = 0; r < 4; r++) acc[i][j][r] = 0.0f;

    const int arow = tid >> 3;
    const int acol = (tid & 7) << 2;

#pragma unroll 1
    for (int kc = 0; kc < 8; kc++) {
        const int k0 = kc * 32;
        // ---- stage A tile (128 x 32) ----
#pragma unroll
        for (int rr = 0; rr < 4; rr++) {
            int r = arow + rr * 32;
            int grow = bm + r;
            float4 v = make_float4(0.f, 0.f, 0.f, 0.f);
            if (grow < M) {
                v = *(const float4*)(A + (size_t)grow * 256 + k0 + acol);
                if (mode == 0) {
                    float s = nm[grow];
                    v.x *= s; v.y *= s; v.z *= s; v.w *= s;
                } else {
                    v.x = fmaxf(v.x, 0.f); v.y = fmaxf(v.y, 0.f);
                    v.z = fmaxf(v.z, 0.f); v.w = fmaxf(v.w, 0.f);
                }
            }
            int base = r * ASTR + acol;
            split1(v.x, &sm.Ahi[base + 0], &sm.Alo[base + 0]);
            split1(v.y, &sm.Ahi[base + 1], &sm.Alo[base + 1]);
            split1(v.z, &sm.Ahi[base + 2], &sm.Alo[base + 2]);
            split1(v.w, &sm.Ahi[base + 3], &sm.Alo[base + 3]);
        }
        // ---- stage B tile (32 x 128) ----
#pragma unroll
        for (int rr = 0; rr < 4; rr++) {
            int idx = tid + rr * 256;
            int r = idx >> 5;
            int c4 = (idx & 31) << 2;
            float4 v = *(const float4*)(B + (size_t)(k0 + r) * 256 + bn + c4);
            int base = r * BSTR + c4;
            split1(v.x, &sm.Bhi[base + 0], &sm.Blo[base + 0]);
            split1(v.y, &sm.Bhi[base + 1], &sm.Blo[base + 1]);
            split1(v.z, &sm.Bhi[base + 2], &sm.Blo[base + 2]);
            split1(v.w, &sm.Bhi[base + 3], &sm.Blo[base + 3]);
        }
        __syncthreads();

#pragma unroll
        for (int kk = 0; kk < 32; kk += 16) {
            uint32_t ah[4][4], al[4][4], bh[4][2], bl[4][2];
            const int ar = (lane & 7) + ((lane >> 3) & 1) * 8;
            const int ac = kk + (lane >> 4) * 8;
#pragma unroll
            for (int ms = 0; ms < 4; ms++) {
                int r = wm + ms * 16 + ar;
                LDSM4(ah[ms][0], ah[ms][1], ah[ms][2], ah[ms][3],
                      smem_u32(&sm.Ahi[r * ASTR + ac]));
                LDSM4(al[ms][0], al[ms][1], al[ms][2], al[ms][3],
                      smem_u32(&sm.Alo[r * ASTR + ac]));
            }
            const int brow = kk + (lane & 7) + ((lane >> 3) & 1) * 8;
#pragma unroll
            for (int g = 0; g < 2; g++) {
                int c = wn + g * 16 + (lane >> 4) * 8;
                uint32_t r0, r1, r2, r3;
                LDSM4T(r0, r1, r2, r3, smem_u32(&sm.Bhi[brow * BSTR + c]));
                bh[g * 2][0] = r0; bh[g * 2][1] = r1;
                bh[g * 2 + 1][0] = r2; bh[g * 2 + 1][1] = r3;
                LDSM4T(r0, r1, r2, r3, smem_u32(&sm.Blo[brow * BSTR + c]));
                bl[g * 2][0] = r0; bl[g * 2][1] = r1;
                bl[g * 2 + 1][0] = r2; bl[g * 2 + 1][1] = r3;
            }
#pragma unroll
            for (int ms = 0; ms < 4; ms++)
#pragma unroll
                for (int ns = 0; ns < 4; ns++) {
                    mma_bf16(acc[ms][ns], ah[ms], bh[ns]);
                    mma_bf16(acc[ms][ns], ah[ms], bl[ns]);
                    mma_bf16(acc[ms][ns], al[ms], bh[ns]);
                }
        }
        __syncthreads();
    }

#pragma unroll
    for (int ms = 0; ms < 4; ms++) {
#pragma unroll
        for (int ns = 0; ns < 4; ns++) {
            int row = bm + wm + ms * 16 + (lane >> 2);
            int col = bn + wn + ns * 8 + (lane & 3) * 2;
            if (row < M) {
                float2 o = make_float2(acc[ms][ns][0], acc[ms][ns][1]);
                *(float2*)(C + (size_t)row * 256 + col) = o;
            }
            if (row + 8 < M) {
                float2 o = make_float2(acc[ms][ns][2], acc[ms][ns][3]);
                *(float2*)(C + (size_t)(row + 8) * 256 + col) = o;
            }
        }
    }
}

// ---------------- batched 3-GEMM (independent projections) -------------------
__global__ void __launch_bounds__(256, 2)
gemm3_mma(const float* __restrict__ A0, const float* __restrict__ A1,
          const float* __restrict__ A2, const float* __restrict__ nm,
          const float* __restrict__ B0, const float* __restrict__ B1,
          const float* __restrict__ B2,
          float* __restrict__ C0, float* __restrict__ C1, float* __restrict__ C2)
{
    __shared__ __align__(16) GemmSmem sm;
    const int z = blockIdx.z;
    const float* A = (z == 0) ? A0 : (z == 1) ? A1 : A2;
    const float* B = (z == 0) ? B0 : (z == 1) ? B1 : B2;
    float* C = (z == 0) ? C0 : (z == 1) ? C1 : C2;
    int mode = (z == 2) ? 1 : 0;
    gemm_body(sm, A, nm, B, C, N_, mode, blockIdx.x * 128, blockIdx.y * 128);
}

// ---------------- single GEMM (layer-2 dst projection) -----------------------
__global__ void __launch_bounds__(256, 2)
gemm_mma(const float* __restrict__ A, const float* __restrict__ nm,
         const float* __restrict__ B, float* __restrict__ C, int M, int mode)
{
    __shared__ __align__(16) GemmSmem sm;
    gemm_body(sm, A, nm, B, C, M, mode, blockIdx.x * 128, blockIdx.y * 128);
}

// ---------------- edge pass 1: scores + exp + segment sum (vectorized) -------
__global__ void score_kernel(const int* __restrict__ srcIdx, const int* __restrict__ dstIdx,
                             const float* __restrict__ hs, const float* __restrict__ hd,
                             const float* __restrict__ a)
{
    int e = (blockIdx.x * blockDim.x + threadIdx.x) >> 5;
    int lane = threadIdx.x & 31;
    if (e >= E_) return;
    int s = srcIdx[e];
    int d = dstIdx[e];
    const float4* hsp = (const float4*)(hs + (size_t)s * 256) + lane * 2;
    const float4* hdp = (const float4*)(hd + (size_t)d * 256) + lane * 2;
    float4 s0 = __ldg(hsp), s1 = __ldg(hsp + 1);
    float4 d0 = __ldg(hdp), d1 = __ldg(hdp + 1);
    const float4* ap = (const float4*)a + lane * 2;
    float4 a0 = __ldg(ap), a1v = __ldg(ap + 1);

    float v, part = 0.0f;
    v = s0.x + d0.x; v = v > 0.f ? v : 0.2f * v; part = fmaf(a0.x, v, part);
    v = s0.y + d0.y; v = v > 0.f ? v : 0.2f * v; part = fmaf(a0.y, v, part);
    v = s0.z + d0.z; v = v > 0.f ? v : 0.2f * v; part = fmaf(a0.z, v, part);
    v = s0.w + d0.w; v = v > 0.f ? v : 0.2f * v; part = fmaf(a0.w, v, part);
    v = s1.x + d1.x; v = v > 0.f ? v : 0.2f * v; part = fmaf(a1v.x, v, part);
    v = s1.y + d1.y; v = v > 0.f ? v : 0.2f * v; part = fmaf(a1v.y, v, part);
    v = s1.z + d1.z; v = v > 0.f ? v : 0.2f * v; part = fmaf(a1v.z, v, part);
    v = s1.w + d1.w; v = v > 0.f ? v : 0.2f * v; part = fmaf(a1v.w, v, part);

    part += __shfl_xor_sync(0xffffffffu, part, 1);
    part += __shfl_xor_sync(0xffffffffu, part, 2);
    part += __shfl_xor_sync(0xffffffffu, part, 4);
    if ((lane & 7) == 0) {
        int h = lane >> 3;
        float p = expf(part);
        g_p[(size_t)e * 4 + h] = p;
        atomicAdd(&g_den[(size_t)d * 4 + h], p);
    }
}

// ---------------- edge pass 2: weighted message aggregation ------------------
__global__ void agg_kernel(const int* __restrict__ srcIdx, const int* __restrict__ dstIdx,
                           const float* __restrict__ emask,
                           const float* __restrict__ hs, float* __restrict__ outp)
{
    int e = (blockIdx.x * blockDim.x + threadIdx.x) >> 5;
    int lane = threadIdx.x & 31;
    if (e >= E_) return;
    int s = srcIdx[e];
    int d = dstIdx[e];
    float em = emask[e];
    float w = 0.0f;
    if (lane < 4)
        w = g_p[(size_t)e * 4 + lane] / (g_den[(size_t)d * 4 + lane] + 1e-16f) * em;
    float wh = __shfl_sync(0xffffffffu, w, lane >> 3);
    const float4* hsp = (const float4*)(hs + (size_t)s * 256 + lane * 8);
    float4 x0 = __ldg(hsp);
    float4 x1 = __ldg(hsp + 1);
    float* op = outp + (size_t)d * 256 + lane * 8;
    redAddV4(op,     wh * x0.x, wh * x0.y, wh * x0.z, wh * x0.w);
    redAddV4(op + 4, wh * x1.x, wh * x1.y, wh * x1.z, wh * x1.w);
}

// ---------------- MMA pool: scores -> softmax -> S^T @ X ---------------------
#define XSTR 264
#define WSTR 72
#define POOL_SMEM (2 * 128 * XSTR * 2 + 2 * 256 * WSTR * 2)

__global__ void __launch_bounds__(256)
pool_mma(const float* __restrict__ X, const float* __restrict__ Wa)
{
    extern __shared__ __align__(16) char smem[];
    unsigned short* Xh = (unsigned short*)smem;
    unsigned short* Xl = Xh + 128 * XSTR;
    unsigned short* Wh = Xl + 128 * XSTR;
    unsigned short* Wl = Wh + 256 * WSTR;
    unsigned short* Sh = Wh;   // reuse after scores done
    unsigned short* Sl = Wl;

    const int tid = threadIdx.x;
    const int lane = tid & 31;
    const int warp = tid >> 5;
    const int row0 = blockIdx.x * 128;

#pragma unroll
    for (int j = 0; j < 32; j++) {
        int idx = tid + j * 256;
        int r = idx >> 6;
        int c4 = (idx & 63) << 2;
        int grow = row0 + r;
        float4 v = make_float4(0.f, 0.f, 0.f, 0.f);
        if (grow < N_) v = *(const float4*)(X + (size_t)grow * 256 + c4);
        int base = r * XSTR + c4;
        split1(v.x, &Xh[base + 0], &Xl[base + 0]);
        split1(v.y, &Xh[base + 1], &Xl[base + 1]);
        split1(v.z, &Xh[base + 2], &Xl[base + 2]);
        split1(v.w, &Xh[base + 3], &Xl[base + 3]);
    }
#pragma unroll
    for (int j = 0; j < 16; j++) {
        int idx = tid + j * 256;
        int r = idx >> 4;
        int c4 = (idx & 15) << 2;
        float4 v = *(const float4*)(Wa + (size_t)r * 64 + c4);
        int base = r * WSTR + c4;
        split1(v.x, &Wh[base + 0], &Wl[base + 0]);
        split1(v.y, &Wh[base + 1], &Wl[base + 1]);
        split1(v.z, &Wh[base + 2], &Wl[base + 2]);
        split1(v.w, &Wh[base + 3], &Wl[base + 3]);
    }
    __syncthreads();

    float sc[8][4];
#pragma unroll
    for (int i = 0; i < 8; i++)
#pragma unroll
        for (int r = 0; r < 4; r++) sc[i][r] = 0.0f;

    const int arow = (lane & 7) + ((lane >> 3) & 1) * 8;
#pragma unroll 1
    for (int k = 0; k < 256; k += 16) {
        uint32_t ah[4], al[4];
        int rbase = (warp * 16 + arow) * XSTR + k + (lane >> 4) * 8;
        LDSM4(ah[0], ah[1], ah[2], ah[3], smem_u32(&Xh[rbase]));
        LDSM4(al[0], al[1], al[2], al[3], smem_u32(&Xl[rbase]));
        uint32_t bh[8][2], bl[8][2];
        int brow = k + (lane & 7) + ((lane >> 3) & 1) * 8;
#pragma unroll
        for (int g = 0; g < 4; g++) {
            int c = g * 16 + (lane >> 4) * 8;
            uint32_t r0, r1, r2, r3;
            LDSM4T(r0, r1, r2, r3, smem_u32(&Wh[brow * WSTR + c]));
            bh[g * 2][0] = r0; bh[g * 2][1] = r1;
            bh[g * 2 + 1][0] = r2; bh[g * 2 + 1][1] = r3;
            LDSM4T(r0, r1, r2, r3, smem_u32(&Wl[brow * WSTR + c]));
            bl[g * 2][0] = r0; bl[g * 2][1] = r1;
            bl[g * 2 + 1][0] = r2; bl[g * 2 + 1][1] = r3;
        }
#pragma unroll
        for (int ns = 0; ns < 8; ns++) {
            mma_bf16(sc[ns], ah, bh[ns]);
            mma_bf16(sc[ns], ah, bl[ns]);
            mma_bf16(sc[ns], al, bh[ns]);
        }
    }

    float mA = -1e30f, mB = -1e30f;
#pragma unroll
    for (int ns = 0; ns < 8; ns++) {
        mA = fmaxf(mA, fmaxf(sc[ns][0], sc[ns][1]));
        mB = fmaxf(mB, fmaxf(sc[ns][2], sc[ns][3]));
    }
    mA = fmaxf(mA, __shfl_xor_sync(0xffffffffu, mA, 1));
    mA = fmaxf(mA, __shfl_xor_sync(0xffffffffu, mA, 2));
    mB = fmaxf(mB, __shfl_xor_sync(0xffffffffu, mB, 1));
    mB = fmaxf(mB, __shfl_xor_sync(0xffffffffu, mB, 2));
    float sumA = 0.0f, sumB = 0.0f;
#pragma unroll
    for (int ns = 0; ns < 8; ns++) {
        sc[ns][0] = expf(sc[ns][0] - mA); sc[ns][1] = expf(sc[ns][1] - mA);
        sc[ns][2] = expf(sc[ns][2] - mB); sc[ns][3] = expf(sc[ns][3] - mB);
        sumA += sc[ns][0] + sc[ns][1];
        sumB += sc[ns][2] + sc[ns][3];
    }
    sumA += __shfl_xor_sync(0xffffffffu, sumA, 1);
    sumA += __shfl_xor_sync(0xffffffffu, sumA, 2);
    sumB += __shfl_xor_sync(0xffffffffu, sumB, 1);
    sumB += __shfl_xor_sync(0xffffffffu, sumB, 2);
    float invA = 1.0f / sumA, invB = 1.0f / sumB;

    __syncthreads();

    {
        int rA = warp * 16 + (lane >> 2);
        int rB = rA + 8;
        int colb = (lane & 3) * 2;
#pragma unroll
        for (int ns = 0; ns < 8; ns++) {
            int col = ns * 8 + colb;
            float a0 = sc[ns][0] * invA, a1 = sc[ns][1] * invA;
            float b0 = sc[ns][2] * invB, b1 = sc[ns][3] * invB;
            *(uint32_t*)&Sh[rA * WSTR + col] = pack_bf2(a0, a1);
            *(uint32_t*)&Sl[rA * WSTR + col] = pack_bf2_lo(a0, a1);
            *(uint32_t*)&Sh[rB * WSTR + col] = pack_bf2(b0, b1);
            *(uint32_t*)&Sl[rB * WSTR + col] = pack_bf2_lo(b0, b1);
        }
    }
    __syncthreads();

    float pc[4][4][4];
#pragma unroll
    for (int i = 0; i < 4; i++)
#pragma unroll
        for (int j = 0; j < 4; j++)
#pragma unroll
            for (int r = 0; r < 4; r++) pc[i][j][r] = 0.0f;

    const int nw = warp * 32;
#pragma unroll 1
    for (int kk = 0; kk < 128; kk += 16) {
        uint32_t sah[4][4], sal[4][4];
        int srow = kk + ((lane >> 4) & 1) * 8 + (lane & 7);
        int scoff = ((lane >> 3) & 1) * 8;
#pragma unroll
        for (int mt = 0; mt < 4; mt++) {
            int sc2 = mt * 16 + scoff;
            LDSM4T(sah[mt][0], sah[mt][1], sah[mt][2], sah[mt][3],
                   smem_u32(&Sh[srow * WSTR + sc2]));
            LDSM4T(sal[mt][0], sal[mt][1], sal[mt][2], sal[mt][3],
                   smem_u32(&Sl[srow * WSTR + sc2]));
        }
        uint32_t xbh[4][2], xbl[4][2];
        int brow = kk + (lane & 7) + ((lane >> 3) & 1) * 8;
#pragma unroll
        for (int g = 0; g < 2; g++) {
            int c = nw + g * 16 + (lane >> 4) * 8;
            uint32_t r0, r1, r2, r3;
            LDSM4T(r0, r1, r2, r3, smem_u32(&Xh[brow * XSTR + c]));
            xbh[g * 2][0] = r0; xbh[g * 2][1] = r1;
            xbh[g * 2 + 1][0] = r2; xbh[g * 2 + 1][1] = r3;
            LDSM4T(r0, r1, r2, r3, smem_u32(&Xl[brow * XSTR + c]));
            xbl[g * 2][0] = r0; xbl[g * 2][1] = r1;
            xbl[g * 2 + 1][0] = r2; xbl[g * 2 + 1][1] = r3;
        }
#pragma unroll
        for (int mt = 0; mt < 4; mt++)
#pragma unroll
            for (int ns = 0; ns < 4; ns++) {
                mma_bf16(pc[mt][ns], sah[mt], xbh[ns]);
                mma_bf16(pc[mt][ns], sah[mt], xbl[ns]);
                mma_bf16(pc[mt][ns], sal[mt], xbh[ns]);
            }
    }

#pragma unroll
    for (int mt = 0; mt < 4; mt++)
#pragma unroll
        for (int ns = 0; ns < 4; ns++) {
            int kidx = mt * 16 + (lane >> 2);
            int col = nw + ns * 8 + (lane & 3) * 2;
            redAddV2(&g_pool[(size_t)kidx * 256 + col], pc[mt][ns][0], pc[mt][ns][1]);
            redAddV2(&g_pool[(size_t)(kidx + 8) * 256 + col], pc[mt][ns][2], pc[mt][ns][3]);
        }
}

// ---------------- edge_attr means over all T ---------------------------------
__global__ void edge_sum_kernel(const float* __restrict__ ea)
{
    int t = blockIdx.y;
    const float* p = ea + (size_t)t * E_;
    float s = 0.0f;
    for (int i = blockIdx.x * blockDim.x + threadIdx.x; i < E_; i += gridDim.x * blockDim.x)
        s += p[i];
#pragma unroll
    for (int o = 16; o; o >>= 1) s += __shfl_xor_sync(0xffffffffu, s, o);
    __shared__ float red[8];
    int lane = threadIdx.x & 31, w = threadIdx.x >> 5;
    if (lane == 0) red[w] = s;
    __syncthreads();
    if (threadIdx.x == 0) {
        float bs = 0.0f;
        for (int i = 0; i < (int)(blockDim.x >> 5); i++) bs += red[i];
        atomicAdd(&g_esum[t], bs);
    }
}

// ---------------- final classifier -------------------------------------------
__global__ void final_kernel(const float* __restrict__ Wcls, const float* __restrict__ bcls,
                             float* __restrict__ out)
{
    int k = blockIdx.x;
    int lane = threadIdx.x;
    float s = 0.0f;
    for (int d = lane; d < 256; d += 32) s += g_pool[(size_t)k * 256 + d] * Wcls[d];
#pragma unroll
    for (int o = 16; o; o >>= 1) s += __shfl_xor_sync(0xffffffffu, s, o);
    if (lane == 0) {
        float extra = 0.0f;
#pragma unroll
        for (int t = 0; t < T_; t++) extra += (g_esum[t] * (1.0f / E_)) * Wcls[256 + t];
        float z = s + extra + bcls[0];
        out[k] = 1.0f / (1.0f + expf(-z));
    }
}

// ---------------- launch -------------------------------------------------------
extern "C" void kernel_launch(void* const* d_in, const int* in_sizes, int n_in,
                              void* d_out, int out_size)
{
    const float* x_pkg = (const float*)d_in[0];
    const float* x_dst = (const float*)d_in[1];
    const int*   eidx  = (const int*)d_in[2];
    const float* eattr = (const float*)d_in[3];
    const float* nmask = (const float*)d_in[4];
    const float* emask = (const float*)d_in[5];
    const float* W1s   = (const float*)d_in[6];
    const float* W1d   = (const float*)d_in[7];
    const float* a1    = (const float*)d_in[8];
    const float* W2s   = (const float*)d_in[9];
    const float* W2d   = (const float*)d_in[10];
    const float* a2    = (const float*)d_in[11];
    const float* Was   = (const float*)d_in[12];
    const float* Wcl   = (const float*)d_in[13];
    const float* bcl   = (const float*)d_in[14];
    float* out = (float*)d_out;

    const int tsel = T_ - 1;
    const int* src5 = eidx + (size_t)tsel * 2 * E_;
    const int* dst5 = src5 + E_;
    const float* x_dst5 = x_dst + (size_t)tsel * N_ * D_;
    const float* W1s5 = W1s + (size_t)tsel * D_ * 256;
    const float* W1d5 = W1d + (size_t)tsel * D_ * 256;
    const float* a1_5 = a1 + (size_t)tsel * 256;
    const float* W2s5 = W2s + (size_t)tsel * D_ * 256;
    const float* W2d5 = W2d + (size_t)tsel * D_ * 256;
    const float* a2_5 = a2 + (size_t)tsel * 256;

    float *hs1, *hd1, *hs2, *hd2, *h1, *h2;
    cudaGetSymbolAddress((void**)&hs1, g_hs1);
    cudaGetSymbolAddress((void**)&hd1, g_hd1);
    cudaGetSymbolAddress((void**)&hs2, g_hs2);
    cudaGetSymbolAddress((void**)&hd2, g_hd2);
    cudaGetSymbolAddress((void**)&h1,  g_h1);
    cudaGetSymbolAddress((void**)&h2,  g_h2);

    cudaFuncSetAttribute(pool_mma, cudaFuncAttributeMaxDynamicSharedMemorySize, POOL_SMEM);

    const int egrid = (E_ + 7) / 8;

    init1_kernel<<<2048, 256>>>();

    // 3 independent projections in ONE batched launch (tail-wave reduction)
    gemm3_mma<<<dim3(391, 2, 3), 256>>>(x_pkg, x_dst5, x_pkg, nmask,
                                        W1s5, W1d5, W2s5, hs1, hd1, hs2);

    score_kernel<<<egrid, 256>>>(src5, dst5, hs1, hd1, a1_5);
    agg_kernel<<<egrid, 256>>>(src5, dst5, emask, hs1, h1);

    gemm_mma<<<dim3(391, 2), 256>>>(h1, nullptr, W2d5, hd2, N_, 1);

    init2_kernel<<<2048, 256>>>();

    score_kernel<<<egrid, 256>>>(src5, dst5, hs2, hd2, a2_5);
    agg_kernel<<<egrid, 256>>>(src5, dst5, emask, hs2, h2);

    edge_sum_kernel<<<dim3(32, T_), 256>>>(eattr);
    pool_mma<<<391, 256, POOL_SMEM>>>(h2, Was);
    final_kernel<<<K_, 32>>>(Wcl, bcl, out);
}

// round 6
// speedup vs baseline: 1.0146x; 1.0146x over previous
#include <cuda_runtime.h>
#include <cuda_bf16.h>
#include <math.h>
#include <stdint.h>

#define N_ 50000
#define D_ 256
#define E_ 250000
#define T_ 6
#define H_ 4
#define K_ 64

// ---------------- scratch (device globals; no runtime allocation) ----------
__device__ float g_hs1[(size_t)N_ * D_];
__device__ float g_hd1[(size_t)N_ * D_];
__device__ float g_hs2[(size_t)N_ * D_];
__device__ float g_hd2[(size_t)N_ * D_];
__device__ float g_h1[(size_t)N_ * D_];
__device__ float g_h2[(size_t)N_ * D_];
__device__ float g_den[(size_t)N_ * H_];
__device__ float g_pool[(size_t)K_ * D_];
__device__ float g_esum[T_];

// ---------------- helpers ---------------------------------------------------
__device__ __forceinline__ void redAddV4(float* p, float a, float b, float c, float d) {
    asm volatile("red.global.add.v4.f32 [%0], {%1,%2,%3,%4};"
                 :: "l"(p), "f"(a), "f"(b), "f"(c), "f"(d) : "memory");
}
__device__ __forceinline__ void redAddV2(float* p, float a, float b) {
    asm volatile("red.global.add.v2.f32 [%0], {%1,%2};"
                 :: "l"(p), "f"(a), "f"(b) : "memory");
}

__device__ __forceinline__ uint32_t smem_u32(const void* p) {
    return (uint32_t)__cvta_generic_to_shared(p);
}

#define LDSM4(R0, R1, R2, R3, ADDR) \
    asm volatile("ldmatrix.sync.aligned.m8n8.x4.shared.b16 {%0,%1,%2,%3}, [%4];" \
                 : "=r"(R0), "=r"(R1), "=r"(R2), "=r"(R3) : "r"(ADDR))

#define LDSM4T(R0, R1, R2, R3, ADDR) \
    asm volatile("ldmatrix.sync.aligned.m8n8.x4.trans.shared.b16 {%0,%1,%2,%3}, [%4];" \
                 : "=r"(R0), "=r"(R1), "=r"(R2), "=r"(R3) : "r"(ADDR))

__device__ __forceinline__ void mma_bf16(float* c, const uint32_t* a, const uint32_t* b) {
    asm volatile("mma.sync.aligned.m16n8k16.row.col.f32.bf16.bf16.f32 "
                 "{%0,%1,%2,%3},{%4,%5,%6,%7},{%8,%9},{%0,%1,%2,%3};"
                 : "+f"(c[0]), "+f"(c[1]), "+f"(c[2]), "+f"(c[3])
                 : "r"(a[0]), "r"(a[1]), "r"(a[2]), "r"(a[3]), "r"(b[0]), "r"(b[1]));
}

__device__ __forceinline__ void split1(float x, unsigned short* hi, unsigned short* lo) {
    __nv_bfloat16 h = __float2bfloat16(x);
    *hi = __bfloat16_as_ushort(h);
    float r = x - __bfloat162float(h);
    *lo = __bfloat16_as_ushort(__float2bfloat16(r));
}

__device__ __forceinline__ uint32_t pack_bf2(float a, float b) {
    __nv_bfloat16 ha = __float2bfloat16(a);
    __nv_bfloat16 hb = __float2bfloat16(b);
    return (uint32_t)__bfloat16_as_ushort(ha) | ((uint32_t)__bfloat16_as_ushort(hb) << 16);
}
__device__ __forceinline__ uint32_t pack_bf2_lo(float a, float b) {
    __nv_bfloat16 ha = __float2bfloat16(a);
    __nv_bfloat16 hb = __float2bfloat16(b);
    float ra = a - __bfloat162float(ha);
    float rb = b - __bfloat162float(hb);
    __nv_bfloat16 la = __float2bfloat16(ra);
    __nv_bfloat16 lb = __float2bfloat16(rb);
    return (uint32_t)__bfloat16_as_ushort(la) | ((uint32_t)__bfloat16_as_ushort(lb) << 16);
}

// ---------------- init kernels ----------------------------------------------
__global__ void init1_kernel() {
    int i = blockIdx.x * blockDim.x + threadIdx.x;
    int st = gridDim.x * blockDim.x;
    for (int j = i; j < N_ * D_; j += st) g_h1[j] = 0.0f;
    for (int j = i; j < N_ * H_; j += st) g_den[j] = 0.0f;
    for (int j = i; j < K_ * D_; j += st) g_pool[j] = 0.0f;
    for (int j = i; j < T_; j += st) g_esum[j] = 0.0f;
}

__global__ void init2_kernel() {
    int i = blockIdx.x * blockDim.x + threadIdx.x;
    int st = gridDim.x * blockDim.x;
    for (int j = i; j < N_ * D_; j += st) g_h2[j] = 0.0f;
    for (int j = i; j < N_ * H_; j += st) g_den[j] = 0.0f;
}

// =============== GEMM: C[M x 256] = f(A)[M x 256] @ B[256 x 256] =============
// mode 0: f = A * nm[row]
// mode 1: f = relu(A)
// mode 2: f = relu(A) / (nm[row*4 + col/64] + 1e-16)   (deferred GAT softmax norm)
struct GemmSmem {
    unsigned short Ahi[128 * 40];
    unsigned short Alo[128 * 40];
    unsigned short Bhi[32 * 136];
    unsigned short Blo[32 * 136];
};

__device__ __forceinline__ void gemm_body(
    GemmSmem& sm, const float* __restrict__ A, const float* __restrict__ nm,
    const float* __restrict__ B, float* __restrict__ C, int M, int mode,
    int bm, int bn)
{
    constexpr int ASTR = 40;
    constexpr int BSTR = 136;
    const int tid = threadIdx.x;
    const int lane = tid & 31;
    const int warp = tid >> 5;
    const int wm = (warp & 1) * 64;
    const int wn = (warp >> 1) * 32;

    float acc[4][4][4];
#pragma unroll
    for (int i = 0; i < 4; i++)
#pragma unroll
        for (int j = 0; j < 4; j++)
#pragma unroll
            for (int r = 0; r < 4; r++) acc[i][j][r] = 0.0f;

    const int arow = tid >> 3;
    const int acol = (tid & 7) << 2;

#pragma unroll 1
    for (int kc = 0; kc < 8; kc++) {
        const int k0 = kc * 32;
        // ---- stage A tile (128 x 32) ----
#pragma unroll
        for (int rr = 0; rr < 4; rr++) {
            int r = arow + rr * 32;
            int grow = bm + r;
            float4 v = make_float4(0.f, 0.f, 0.f, 0.f);
            if (grow < M) {
                v = *(const float4*)(A + (size_t)grow * 256 + k0 + acol);
                if (mode == 0) {
                    float s = nm[grow];
                    v.x *= s; v.y *= s; v.z *= s; v.w *= s;
                } else if (mode == 1) {
                    v.x = fmaxf(v.x, 0.f); v.y = fmaxf(v.y, 0.f);
                    v.z = fmaxf(v.z, 0.f); v.w = fmaxf(v.w, 0.f);
                } else {
                    int head = (k0 + acol) >> 6;
                    float inv = 1.0f / (nm[(size_t)grow * 4 + head] + 1e-16f);
                    v.x = fmaxf(v.x, 0.f) * inv; v.y = fmaxf(v.y, 0.f) * inv;
                    v.z = fmaxf(v.z, 0.f) * inv; v.w = fmaxf(v.w, 0.f) * inv;
                }
            }
            int base = r * ASTR + acol;
            split1(v.x, &sm.Ahi[base + 0], &sm.Alo[base + 0]);
            split1(v.y, &sm.Ahi[base + 1], &sm.Alo[base + 1]);
            split1(v.z, &sm.Ahi[base + 2], &sm.Alo[base + 2]);
            split1(v.w, &sm.Ahi[base + 3], &sm.Alo[base + 3]);
        }
        // ---- stage B tile (32 x 128) ----
#pragma unroll
        for (int rr = 0; rr < 4; rr++) {
            int idx = tid + rr * 256;
            int r = idx >> 5;
            int c4 = (idx & 31) << 2;
            float4 v = *(const float4*)(B + (size_t)(k0 + r) * 256 + bn + c4);
            int base = r * BSTR + c4;
            split1(v.x, &sm.Bhi[base + 0], &sm.Blo[base + 0]);
            split1(v.y, &sm.Bhi[base + 1], &sm.Blo[base + 1]);
            split1(v.z, &sm.Bhi[base + 2], &sm.Blo[base + 2]);
            split1(v.w, &sm.Bhi[base + 3], &sm.Blo[base + 3]);
        }
        __syncthreads();

#pragma unroll
        for (int kk = 0; kk < 32; kk += 16) {
            uint32_t ah[4][4], al[4][4], bh[4][2], bl[4][2];
            const int ar = (lane & 7) + ((lane >> 3) & 1) * 8;
            const int ac = kk + (lane >> 4) * 8;
#pragma unroll
            for (int ms = 0; ms < 4; ms++) {
                int r = wm + ms * 16 + ar;
                LDSM4(ah[ms][0], ah[ms][1], ah[ms][2], ah[ms][3],
                      smem_u32(&sm.Ahi[r * ASTR + ac]));
                LDSM4(al[ms][0], al[ms][1], al[ms][2], al[ms][3],
                      smem_u32(&sm.Alo[r * ASTR + ac]));
            }
            const int brow = kk + (lane & 7) + ((lane >> 3) & 1) * 8;
#pragma unroll
            for (int g = 0; g < 2; g++) {
                int c = wn + g * 16 + (lane >> 4) * 8;
                uint32_t r0, r1, r2, r3;
                LDSM4T(r0, r1, r2, r3, smem_u32(&sm.Bhi[brow * BSTR + c]));
                bh[g * 2][0] = r0; bh[g * 2][1] = r1;
                bh[g * 2 + 1][0] = r2; bh[g * 2 + 1][1] = r3;
                LDSM4T(r0, r1, r2, r3, smem_u32(&sm.Blo[brow * BSTR + c]));
                bl[g * 2][0] = r0; bl[g * 2][1] = r1;
                bl[g * 2 + 1][0] = r2; bl[g * 2 + 1][1] = r3;
            }
#pragma unroll
            for (int ms = 0; ms < 4; ms++)
#pragma unroll
                for (int ns = 0; ns < 4; ns++) {
                    mma_bf16(acc[ms][ns], ah[ms], bh[ns]);
                    mma_bf16(acc[ms][ns], ah[ms], bl[ns]);
                    mma_bf16(acc[ms][ns], al[ms], bh[ns]);
                }
        }
        __syncthreads();
    }

#pragma unroll
    for (int ms = 0; ms < 4; ms++) {
#pragma unroll
        for (int ns = 0; ns < 4; ns++) {
            int row = bm + wm + ms * 16 + (lane >> 2);
            int col = bn + wn + ns * 8 + (lane & 3) * 2;
            if (row < M) {
                float2 o = make_float2(acc[ms][ns][0], acc[ms][ns][1]);
                *(float2*)(C + (size_t)row * 256 + col) = o;
            }
            if (row + 8 < M) {
                float2 o = make_float2(acc[ms][ns][2], acc[ms][ns][3]);
                *(float2*)(C + (size_t)(row + 8) * 256 + col) = o;
            }
        }
    }
}

__global__ void __launch_bounds__(256, 2)
gemm_mma(const float* __restrict__ A, const float* __restrict__ nm,
         const float* __restrict__ B, float* __restrict__ C, int M, int mode)
{
    __shared__ __align__(16) GemmSmem sm;
    gemm_body(sm, A, nm, B, C, M, mode, blockIdx.x * 128, blockIdx.y * 128);
}

// ---------------- fused edge pass: score + exp + den + UNNORMALIZED agg ------
// out[d] += exp(e) * ew * hs[s]  ;  den[d][h] += exp(e)
// (consumers divide by den+1e-16; softmax max-shift dropped: |e| <~ 3)
__global__ void edge_fused_kernel(const int* __restrict__ srcIdx,
                                  const int* __restrict__ dstIdx,
                                  const float* __restrict__ emask,
                                  const float* __restrict__ hs,
                                  const float* __restrict__ hd,
                                  const float* __restrict__ a,
                                  float* __restrict__ outp)
{
    int e = (blockIdx.x * blockDim.x + threadIdx.x) >> 5;
    int lane = threadIdx.x & 31;
    if (e >= E_) return;
    int s = srcIdx[e];
    int d = dstIdx[e];
    float em = emask[e];
    const float4* hsp = (const float4*)(hs + (size_t)s * 256) + lane * 2;
    const float4* hdp = (const float4*)(hd + (size_t)d * 256) + lane * 2;
    float4 s0 = __ldg(hsp), s1 = __ldg(hsp + 1);
    float4 d0 = __ldg(hdp), d1 = __ldg(hdp + 1);
    const float4* ap = (const float4*)a + lane * 2;
    float4 a0 = __ldg(ap), a1v = __ldg(ap + 1);

    float v, part = 0.0f;
    v = s0.x + d0.x; v = v > 0.f ? v : 0.2f * v; part = fmaf(a0.x, v, part);
    v = s0.y + d0.y; v = v > 0.f ? v : 0.2f * v; part = fmaf(a0.y, v, part);
    v = s0.z + d0.z; v = v > 0.f ? v : 0.2f * v; part = fmaf(a0.z, v, part);
    v = s0.w + d0.w; v = v > 0.f ? v : 0.2f * v; part = fmaf(a0.w, v, part);
    v = s1.x + d1.x; v = v > 0.f ? v : 0.2f * v; part = fmaf(a1v.x, v, part);
    v = s1.y + d1.y; v = v > 0.f ? v : 0.2f * v; part = fmaf(a1v.y, v, part);
    v = s1.z + d1.z; v = v > 0.f ? v : 0.2f * v; part = fmaf(a1v.z, v, part);
    v = s1.w + d1.w; v = v > 0.f ? v : 0.2f * v; part = fmaf(a1v.w, v, part);

    // segmented reduce within each 8-lane group -> every lane holds its head sum
    part += __shfl_xor_sync(0xffffffffu, part, 1);
    part += __shfl_xor_sync(0xffffffffu, part, 2);
    part += __shfl_xor_sync(0xffffffffu, part, 4);

    float p = expf(part);               // per-head score, all lanes of group
    if ((lane & 7) == 0)
        atomicAdd(&g_den[(size_t)d * 4 + (lane >> 3)], p);

    // this lane's 8 output cols all belong to head (lane>>3) == its group
    float wh = p * em;
    float* op = outp + (size_t)d * 256 + lane * 8;
    redAddV4(op,     wh * s0.x, wh * s0.y, wh * s0.z, wh * s0.w);
    redAddV4(op + 4, wh * s1.x, wh * s1.y, wh * s1.z, wh * s1.w);
}

// ---------------- MMA pool: normalize X -> scores -> softmax -> S^T @ X ------
#define XSTR 264
#define WSTR 72
#define POOL_SMEM (2 * 128 * XSTR * 2 + 2 * 256 * WSTR * 2)

__global__ void __launch_bounds__(256)
pool_mma(const float* __restrict__ X, const float* __restrict__ den,
         const float* __restrict__ Wa)
{
    extern __shared__ __align__(16) char smem[];
    unsigned short* Xh = (unsigned short*)smem;
    unsigned short* Xl = Xh + 128 * XSTR;
    unsigned short* Wh = Xl + 128 * XSTR;
    unsigned short* Wl = Wh + 256 * WSTR;
    unsigned short* Sh = Wh;   // reuse after scores done
    unsigned short* Sl = Wl;

    const int tid = threadIdx.x;
    const int lane = tid & 31;
    const int warp = tid >> 5;
    const int row0 = blockIdx.x * 128;

#pragma unroll
    for (int j = 0; j < 32; j++) {
        int idx = tid + j * 256;
        int r = idx >> 6;
        int c4 = (idx & 63) << 2;
        int grow = row0 + r;
        float4 v = make_float4(0.f, 0.f, 0.f, 0.f);
        if (grow < N_) {
            v = *(const float4*)(X + (size_t)grow * 256 + c4);
            float inv = 1.0f / (den[(size_t)grow * 4 + (c4 >> 6)] + 1e-16f);
            v.x *= inv; v.y *= inv; v.z *= inv; v.w *= inv;
        }
        int base = r * XSTR + c4;
        split1(v.x, &Xh[base + 0], &Xl[base + 0]);
        split1(v.y, &Xh[base + 1], &Xl[base + 1]);
        split1(v.z, &Xh[base + 2], &Xl[base + 2]);
        split1(v.w, &Xh[base + 3], &Xl[base + 3]);
    }
#pragma unroll
    for (int j = 0; j < 16; j++) {
        int idx = tid + j * 256;
        int r = idx >> 4;
        int c4 = (idx & 15) << 2;
        float4 v = *(const float4*)(Wa + (size_t)r * 64 + c4);
        int base = r * WSTR + c4;
        split1(v.x, &Wh[base + 0], &Wl[base + 0]);
        split1(v.y, &Wh[base + 1], &Wl[base + 1]);
        split1(v.z, &Wh[base + 2], &Wl[base + 2]);
        split1(v.w, &Wh[base + 3], &Wl[base + 3]);
    }
    __syncthreads();

    float sc[8][4];
#pragma unroll
    for (int i = 0; i < 8; i++)
#pragma unroll
        for (int r = 0; r < 4; r++) sc[i][r] = 0.0f;

    const int arow = (lane & 7) + ((lane >> 3) & 1) * 8;
#pragma unroll 1
    for (int k = 0; k < 256; k += 16) {
        uint32_t ah[4], al[4];
        int rbase = (warp * 16 + arow) * XSTR + k + (lane >> 4) * 8;
        LDSM4(ah[0], ah[1], ah[2], ah[3], smem_u32(&Xh[rbase]));
        LDSM4(al[0], al[1], al[2], al[3], smem_u32(&Xl[rbase]));
        uint32_t bh[8][2], bl[8][2];
        int brow = k + (lane & 7) + ((lane >> 3) & 1) * 8;
#pragma unroll
        for (int g = 0; g < 4; g++) {
            int c = g * 16 + (lane >> 4) * 8;
            uint32_t r0, r1, r2, r3;
            LDSM4T(r0, r1, r2, r3, smem_u32(&Wh[brow * WSTR + c]));
            bh[g * 2][0] = r0; bh[g * 2][1] = r1;
            bh[g * 2 + 1][0] = r2; bh[g * 2 + 1][1] = r3;
            LDSM4T(r0, r1, r2, r3, smem_u32(&Wl[brow * WSTR + c]));
            bl[g * 2][0] = r0; bl[g * 2][1] = r1;
            bl[g * 2 + 1][0] = r2; bl[g * 2 + 1][1] = r3;
        }
#pragma unroll
        for (int ns = 0; ns < 8; ns++) {
            mma_bf16(sc[ns], ah, bh[ns]);
            mma_bf16(sc[ns], ah, bl[ns]);
            mma_bf16(sc[ns], al, bh[ns]);
        }
    }

    float mA = -1e30f, mB = -1e30f;
#pragma unroll
    for (int ns = 0; ns < 8; ns++) {
        mA = fmaxf(mA, fmaxf(sc[ns][0], sc[ns][1]));
        mB = fmaxf(mB, fmaxf(sc[ns][2], sc[ns][3]));
    }
    mA = fmaxf(mA, __shfl_xor_sync(0xffffffffu, mA, 1));
    mA = fmaxf(mA, __shfl_xor_sync(0xffffffffu, mA, 2));
    mB = fmaxf(mB, __shfl_xor_sync(0xffffffffu, mB, 1));
    mB = fmaxf(mB, __shfl_xor_sync(0xffffffffu, mB, 2));
    float sumA = 0.0f, sumB = 0.0f;
#pragma unroll
    for (int ns = 0; ns < 8; ns++) {
        sc[ns][0] = expf(sc[ns][0] - mA); sc[ns][1] = expf(sc[ns][1] - mA);
        sc[ns][2] = expf(sc[ns][2] - mB); sc[ns][3] = expf(sc[ns][3] - mB);
        sumA += sc[ns][0] + sc[ns][1];
        sumB += sc[ns][2] + sc[ns][3];
    }
    sumA += __shfl_xor_sync(0xffffffffu, sumA, 1);
    sumA += __shfl_xor_sync(0xffffffffu, sumA, 2);
    sumB += __shfl_xor_sync(0xffffffffu, sumB, 1);
    sumB += __shfl_xor_sync(0xffffffffu, sumB, 2);
    float invA = 1.0f / sumA, invB = 1.0f / sumB;

    __syncthreads();

    {
        int rA = warp * 16 + (lane >> 2);
        int rB = rA + 8;
        int colb = (lane & 3) * 2;
#pragma unroll
        for (int ns = 0; ns < 8; ns++) {
            int col = ns * 8 + colb;
            float a0 = sc[ns][0] * invA, a1 = sc[ns][1] * invA;
            float b0 = sc[ns][2] * invB, b1 = sc[ns][3] * invB;
            *(uint32_t*)&Sh[rA * WSTR + col] = pack_bf2(a0, a1);
            *(uint32_t*)&Sl[rA * WSTR + col] = pack_bf2_lo(a0, a1);
            *(uint32_t*)&Sh[rB * WSTR + col] = pack_bf2(b0, b1);
            *(uint32_t*)&Sl[rB * WSTR + col] = pack_bf2_lo(b0, b1);
        }
    }
    __syncthreads();

    float pc[4][4][4];
#pragma unroll
    for (int i = 0; i < 4; i++)
#pragma unroll
        for (int j = 0; j < 4; j++)
#pragma unroll
            for (int r = 0; r < 4; r++) pc[i][j][r] = 0.0f;

    const int nw = warp * 32;
#pragma unroll 1
    for (int kk = 0; kk < 128; kk += 16) {
        uint32_t sah[4][4], sal[4][4];
        int srow = kk + ((lane >> 4) & 1) * 8 + (lane & 7);
        int scoff = ((lane >> 3) & 1) * 8;
#pragma unroll
        for (int mt = 0; mt < 4; mt++) {
            int sc2 = mt * 16 + scoff;
            LDSM4T(sah[mt][0], sah[mt][1], sah[mt][2], sah[mt][3],
                   smem_u32(&Sh[srow * WSTR + sc2]));
            LDSM4T(sal[mt][0], sal[mt][1], sal[mt][2], sal[mt][3],
                   smem_u32(&Sl[srow * WSTR + sc2]));
        }
        uint32_t xbh[4][2], xbl[4][2];
        int brow = kk + (lane & 7) + ((lane >> 3) & 1) * 8;
#pragma unroll
        for (int g = 0; g < 2; g++) {
            int c = nw + g * 16 + (lane >> 4) * 8;
            uint32_t r0, r1, r2, r3;
            LDSM4T(r0, r1, r2, r3, smem_u32(&Xh[brow * XSTR + c]));
            xbh[g * 2][0] = r0; xbh[g * 2][1] = r1;
            xbh[g * 2 + 1][0] = r2; xbh[g * 2 + 1][1] = r3;
            LDSM4T(r0, r1, r2, r3, smem_u32(&Xl[brow * XSTR + c]));
            xbl[g * 2][0] = r0; xbl[g * 2][1] = r1;
            xbl[g * 2 + 1][0] = r2; xbl[g * 2 + 1][1] = r3;
        }
#pragma unroll
        for (int mt = 0; mt < 4; mt++)
#pragma unroll
            for (int ns = 0; ns < 4; ns++) {
                mma_bf16(pc[mt][ns], sah[mt], xbh[ns]);
                mma_bf16(pc[mt][ns], sah[mt], xbl[ns]);
                mma_bf16(pc[mt][ns], sal[mt], xbh[ns]);
            }
    }

#pragma unroll
    for (int mt = 0; mt < 4; mt++)
#pragma unroll
        for (int ns = 0; ns < 4; ns++) {
            int kidx = mt * 16 + (lane >> 2);
            int col = nw + ns * 8 + (lane & 3) * 2;
            redAddV2(&g_pool[(size_t)kidx * 256 + col], pc[mt][ns][0], pc[mt][ns][1]);
            redAddV2(&g_pool[(size_t)(kidx + 8) * 256 + col], pc[mt][ns][2], pc[mt][ns][3]);
        }
}

// ---------------- edge_attr means over all T ---------------------------------
__global__ void edge_sum_kernel(const float* __restrict__ ea)
{
    int t = blockIdx.y;
    const float* p = ea + (size_t)t * E_;
    float s = 0.0f;
    for (int i = blockIdx.x * blockDim.x + threadIdx.x; i < E_; i += gridDim.x * blockDim.x)
        s += p[i];
#pragma unroll
    for (int o = 16; o; o >>= 1) s += __shfl_xor_sync(0xffffffffu, s, o);
    __shared__ float red[8];
    int lane = threadIdx.x & 31, w = threadIdx.x >> 5;
    if (lane == 0) red[w] = s;
    __syncthreads();
    if (threadIdx.x == 0) {
        float bs = 0.0f;
        for (int i = 0; i < (int)(blockDim.x >> 5); i++) bs += red[i];
        atomicAdd(&g_esum[t], bs);
    }
}

// ---------------- final classifier -------------------------------------------
__global__ void final_kernel(const float* __restrict__ Wcls, const float* __restrict__ bcls,
                             float* __restrict__ out)
{
    int k = blockIdx.x;
    int lane = threadIdx.x;
    float s = 0.0f;
    for (int d = lane; d < 256; d += 32) s += g_pool[(size_t)k * 256 + d] * Wcls[d];
#pragma unroll
    for (int o = 16; o; o >>= 1) s += __shfl_xor_sync(0xffffffffu, s, o);
    if (lane == 0) {
        float extra = 0.0f;
#pragma unroll
        for (int t = 0; t < T_; t++) extra += (g_esum[t] * (1.0f / E_)) * Wcls[256 + t];
        float z = s + extra + bcls[0];
        out[k] = 1.0f / (1.0f + expf(-z));
    }
}

// ---------------- launch -------------------------------------------------------
extern "C" void kernel_launch(void* const* d_in, const int* in_sizes, int n_in,
                              void* d_out, int out_size)
{
    const float* x_pkg = (const float*)d_in[0];
    const float* x_dst = (const float*)d_in[1];
    const int*   eidx  = (const int*)d_in[2];
    const float* eattr = (const float*)d_in[3];
    const float* nmask = (const float*)d_in[4];
    const float* emask = (const float*)d_in[5];
    const float* W1s   = (const float*)d_in[6];
    const float* W1d   = (const float*)d_in[7];
    const float* a1    = (const float*)d_in[8];
    const float* W2s   = (const float*)d_in[9];
    const float* W2d   = (const float*)d_in[10];
    const float* a2    = (const float*)d_in[11];
    const float* Was   = (const float*)d_in[12];
    const float* Wcl   = (const float*)d_in[13];
    const float* bcl   = (const float*)d_in[14];
    float* out = (float*)d_out;

    const int tsel = T_ - 1;
    const int* src5 = eidx + (size_t)tsel * 2 * E_;
    const int* dst5 = src5 + E_;
    const float* x_dst5 = x_dst + (size_t)tsel * N_ * D_;
    const float* W1s5 = W1s + (size_t)tsel * D_ * 256;
    const float* W1d5 = W1d + (size_t)tsel * D_ * 256;
    const float* a1_5 = a1 + (size_t)tsel * 256;
    const float* W2s5 = W2s + (size_t)tsel * D_ * 256;
    const float* W2d5 = W2d + (size_t)tsel * D_ * 256;
    const float* a2_5 = a2 + (size_t)tsel * 256;

    float *hs1, *hd1, *hs2, *hd2, *h1, *h2, *den;
    cudaGetSymbolAddress((void**)&hs1, g_hs1);
    cudaGetSymbolAddress((void**)&hd1, g_hd1);
    cudaGetSymbolAddress((void**)&hs2, g_hs2);
    cudaGetSymbolAddress((void**)&hd2, g_hd2);
    cudaGetSymbolAddress((void**)&h1,  g_h1);
    cudaGetSymbolAddress((void**)&h2,  g_h2);
    cudaGetSymbolAddress((void**)&den, g_den);

    cudaFuncSetAttribute(pool_mma, cudaFuncAttributeMaxDynamicSharedMemorySize, POOL_SMEM);

    dim3 ggrid(391, 2);
    const int egrid = (E_ + 7) / 8;

    init1_kernel<<<2048, 256>>>();

    gemm_mma<<<ggrid, 256>>>(x_pkg,  nmask, W1s5, hs1, N_, 0);
    gemm_mma<<<ggrid, 256>>>(x_dst5, nmask, W1d5, hd1, N_, 0);
    gemm_mma<<<ggrid, 256>>>(x_pkg,  nullptr, W2s5, hs2, N_, 1);

    // layer 1: fused score+exp+den+unnormalized-agg
    edge_fused_kernel<<<egrid, 256>>>(src5, dst5, emask, hs1, hd1, a1_5, h1);

    // layer-2 dst projection; normalization (den1) + relu folded into A-staging
    gemm_mma<<<ggrid, 256>>>(h1, den, W2d5, hd2, N_, 2);

    init2_kernel<<<2048, 256>>>();   // zero h2 + den (after gemm consumed den1)

    // layer 2: fused edge pass
    edge_fused_kernel<<<egrid, 256>>>(src5, dst5, emask, hs2, hd2, a2_5, h2);

    edge_sum_kernel<<<dim3(32, T_), 256>>>(eattr);
    pool_mma<<<391, 256, POOL_SMEM>>>(h2, den, Was);   // den2 normalization folded in
    final_kernel<<<K_, 32>>>(Wcl, bcl, out);
}

// round 7
// speedup vs baseline: 1.0680x; 1.0526x over previous
#include <cuda_runtime.h>
#include <cuda_bf16.h>
#include <math.h>
#include <stdint.h>

#define N_ 50000
#define D_ 256
#define E_ 250000
#define T_ 6
#define H_ 4
#define K_ 64

// ---------------- scratch (device globals; no runtime allocation) ----------
__device__ float g_hs1[(size_t)N_ * D_];
__device__ float g_hd1[(size_t)N_ * D_];
__device__ float g_hs2[(size_t)N_ * D_];
__device__ float g_hd2[(size_t)N_ * D_];
__device__ float g_h1[(size_t)N_ * D_];
__device__ float g_h2[(size_t)N_ * D_];
__device__ float g_den[(size_t)N_ * H_];
__device__ float g_pool[(size_t)K_ * D_];
__device__ float g_esum[T_];
// pre-split weight matrices (bf16 hi/lo), 4 x 256x256
__device__ unsigned short g_Whi[4 * 65536];
__device__ unsigned short g_Wlo[4 * 65536];

// ---------------- helpers ---------------------------------------------------
__device__ __forceinline__ void redAddV4(float* p, float a, float b, float c, float d) {
    asm volatile("red.global.add.v4.f32 [%0], {%1,%2,%3,%4};"
                 :: "l"(p), "f"(a), "f"(b), "f"(c), "f"(d) : "memory");
}
__device__ __forceinline__ void redAddV2(float* p, float a, float b) {
    asm volatile("red.global.add.v2.f32 [%0], {%1,%2};"
                 :: "l"(p), "f"(a), "f"(b) : "memory");
}

__device__ __forceinline__ uint32_t smem_u32(const void* p) {
    return (uint32_t)__cvta_generic_to_shared(p);
}

#define LDSM4(R0, R1, R2, R3, ADDR) \
    asm volatile("ldmatrix.sync.aligned.m8n8.x4.shared.b16 {%0,%1,%2,%3}, [%4];" \
                 : "=r"(R0), "=r"(R1), "=r"(R2), "=r"(R3) : "r"(ADDR))

#define LDSM4T(R0, R1, R2, R3, ADDR) \
    asm volatile("ldmatrix.sync.aligned.m8n8.x4.trans.shared.b16 {%0,%1,%2,%3}, [%4];" \
                 : "=r"(R0), "=r"(R1), "=r"(R2), "=r"(R3) : "r"(ADDR))

__device__ __forceinline__ void mma_bf16(float* c, const uint32_t* a, const uint32_t* b) {
    asm volatile("mma.sync.aligned.m16n8k16.row.col.f32.bf16.bf16.f32 "
                 "{%0,%1,%2,%3},{%4,%5,%6,%7},{%8,%9},{%0,%1,%2,%3};"
                 : "+f"(c[0]), "+f"(c[1]), "+f"(c[2]), "+f"(c[3])
                 : "r"(a[0]), "r"(a[1]), "r"(a[2]), "r"(a[3]), "r"(b[0]), "r"(b[1]));
}

__device__ __forceinline__ void split1(float x, unsigned short* hi, unsigned short* lo) {
    __nv_bfloat16 h = __float2bfloat16(x);
    *hi = __bfloat16_as_ushort(h);
    float r = x - __bfloat162float(h);
    *lo = __bfloat16_as_ushort(__float2bfloat16(r));
}

__device__ __forceinline__ uint32_t pack_bf2(float a, float b) {
    __nv_bfloat16 ha = __float2bfloat16(a);
    __nv_bfloat16 hb = __float2bfloat16(b);
    return (uint32_t)__bfloat16_as_ushort(ha) | ((uint32_t)__bfloat16_as_ushort(hb) << 16);
}
__device__ __forceinline__ uint32_t pack_bf2_lo(float a, float b) {
    __nv_bfloat16 ha = __float2bfloat16(a);
    __nv_bfloat16 hb = __float2bfloat16(b);
    float ra = a - __bfloat162float(ha);
    float rb = b - __bfloat162float(hb);
    __nv_bfloat16 la = __float2bfloat16(ra);
    __nv_bfloat16 lb = __float2bfloat16(rb);
    return (uint32_t)__bfloat16_as_ushort(la) | ((uint32_t)__bfloat16_as_ushort(lb) << 16);
}

// ---------------- init kernels ----------------------------------------------
__global__ void init1_kernel() {
    int i = blockIdx.x * blockDim.x + threadIdx.x;
    int st = gridDim.x * blockDim.x;
    for (int j = i; j < N_ * D_; j += st) g_h1[j] = 0.0f;
    for (int j = i; j < N_ * H_; j += st) g_den[j] = 0.0f;
    for (int j = i; j < K_ * D_; j += st) g_pool[j] = 0.0f;
    for (int j = i; j < T_; j += st) g_esum[j] = 0.0f;
}

__global__ void init2_kernel() {
    int i = blockIdx.x * blockDim.x + threadIdx.x;
    int st = gridDim.x * blockDim.x;
    for (int j = i; j < N_ * D_; j += st) g_h2[j] = 0.0f;
    for (int j = i; j < N_ * H_; j += st) g_den[j] = 0.0f;
}

// ---------------- pre-split 4 weight matrices into bf16 hi/lo ----------------
__global__ void split_w_kernel(const float* __restrict__ W0, const float* __restrict__ W1,
                               const float* __restrict__ W2, const float* __restrict__ W3)
{
    int i = blockIdx.x * blockDim.x + threadIdx.x;   // 0..65535
    int w = blockIdx.y;
    const float* Ws = (w == 0) ? W0 : (w == 1) ? W1 : (w == 2) ? W2 : W3;
    split1(Ws[i], &g_Whi[w * 65536 + i], &g_Wlo[w * 65536 + i]);
}

// =============== GEMM: C[M x 256] = f(A)[M x 256] @ B[256 x 256] =============
// MODE 0: f = A * nm[row]
// MODE 1: f = relu(A)
// MODE 2: f = relu(A) / (nm[row*4 + col/64] + 1e-16)   (deferred GAT softmax norm)
// B comes pre-split (bf16 hi/lo, row-major 256x256).
struct GemmSmem {
    unsigned short Ahi[128 * 40];
    unsigned short Alo[128 * 40];
    unsigned short Bhi[32 * 136];
    unsigned short Blo[32 * 136];
};

template <int MODE>
__device__ __forceinline__ void gemm_body(
    GemmSmem& sm, const float* __restrict__ A, const float* __restrict__ nm,
    const unsigned short* __restrict__ Bhi, const unsigned short* __restrict__ Blo,
    float* __restrict__ C, int M, int bm, int bn)
{
    constexpr int ASTR = 40;
    constexpr int BSTR = 136;
    const int tid = threadIdx.x;
    const int lane = tid & 31;
    const int warp = tid >> 5;
    const int wm = (warp & 1) * 64;
    const int wn = (warp >> 1) * 32;

    float acc[4][4][4];
#pragma unroll
    for (int i = 0; i < 4; i++)
#pragma unroll
        for (int j = 0; j < 4; j++)
#pragma unroll
            for (int r = 0; r < 4; r++) acc[i][j][r] = 0.0f;

    const int arow = tid >> 3;
    const int acol = (tid & 7) << 2;

#pragma unroll 1
    for (int kc = 0; kc < 8; kc++) {
        const int k0 = kc * 32;
        // ---- stage A tile (128 x 32, f32 -> hi/lo bf16 with transform) ----
#pragma unroll
        for (int rr = 0; rr < 4; rr++) {
            int r = arow + rr * 32;
            int grow = bm + r;
            float4 v = make_float4(0.f, 0.f, 0.f, 0.f);
            if (grow < M) {
                v = *(const float4*)(A + (size_t)grow * 256 + k0 + acol);
                if (MODE == 0) {
                    float s = nm[grow];
                    v.x *= s; v.y *= s; v.z *= s; v.w *= s;
                } else if (MODE == 1) {
                    v.x = fmaxf(v.x, 0.f); v.y = fmaxf(v.y, 0.f);
                    v.z = fmaxf(v.z, 0.f); v.w = fmaxf(v.w, 0.f);
                } else {
                    int head = (k0 + acol) >> 6;
                    float inv = 1.0f / (nm[(size_t)grow * 4 + head] + 1e-16f);
                    v.x = fmaxf(v.x, 0.f) * inv; v.y = fmaxf(v.y, 0.f) * inv;
                    v.z = fmaxf(v.z, 0.f) * inv; v.w = fmaxf(v.w, 0.f) * inv;
                }
            }
            int base = r * ASTR + acol;
            split1(v.x, &sm.Ahi[base + 0], &sm.Alo[base + 0]);
            split1(v.y, &sm.Ahi[base + 1], &sm.Alo[base + 1]);
            split1(v.z, &sm.Ahi[base + 2], &sm.Alo[base + 2]);
            split1(v.w, &sm.Ahi[base + 3], &sm.Alo[base + 3]);
        }
        // ---- stage B tile (32 x 128, pre-split bf16: straight uint4 copies) --
#pragma unroll
        for (int rr = 0; rr < 2; rr++) {
            int idx = tid + rr * 256;        // 0..511
            int r = idx >> 4;                // 0..31
            int c8 = (idx & 15) << 3;        // 0..120
            uint4 vh = *(const uint4*)(Bhi + (size_t)(k0 + r) * 256 + bn + c8);
            uint4 vl = *(const uint4*)(Blo + (size_t)(k0 + r) * 256 + bn + c8);
            *(uint4*)&sm.Bhi[r * BSTR + c8] = vh;
            *(uint4*)&sm.Blo[r * BSTR + c8] = vl;
        }
        __syncthreads();

#pragma unroll
        for (int kk = 0; kk < 32; kk += 16) {
            uint32_t ah[4][4], al[4][4], bh[4][2], bl[4][2];
            const int ar = (lane & 7) + ((lane >> 3) & 1) * 8;
            const int ac = kk + (lane >> 4) * 8;
#pragma unroll
            for (int ms = 0; ms < 4; ms++) {
                int r = wm + ms * 16 + ar;
                LDSM4(ah[ms][0], ah[ms][1], ah[ms][2], ah[ms][3],
                      smem_u32(&sm.Ahi[r * ASTR + ac]));
                LDSM4(al[ms][0], al[ms][1], al[ms][2], al[ms][3],
                      smem_u32(&sm.Alo[r * ASTR + ac]));
            }
            const int brow = kk + (lane & 7) + ((lane >> 3) & 1) * 8;
#pragma unroll
            for (int g = 0; g < 2; g++) {
                int c = wn + g * 16 + (lane >> 4) * 8;
                uint32_t r0, r1, r2, r3;
                LDSM4T(r0, r1, r2, r3, smem_u32(&sm.Bhi[brow * BSTR + c]));
                bh[g * 2][0] = r0; bh[g * 2][1] = r1;
                bh[g * 2 + 1][0] = r2; bh[g * 2 + 1][1] = r3;
                LDSM4T(r0, r1, r2, r3, smem_u32(&sm.Blo[brow * BSTR + c]));
                bl[g * 2][0] = r0; bl[g * 2][1] = r1;
                bl[g * 2 + 1][0] = r2; bl[g * 2 + 1][1] = r3;
            }
#pragma unroll
            for (int ms = 0; ms < 4; ms++)
#pragma unroll
                for (int ns = 0; ns < 4; ns++) {
                    mma_bf16(acc[ms][ns], ah[ms], bh[ns]);
                    mma_bf16(acc[ms][ns], ah[ms], bl[ns]);
                    mma_bf16(acc[ms][ns], al[ms], bh[ns]);
                }
        }
        __syncthreads();
    }

#pragma unroll
    for (int ms = 0; ms < 4; ms++) {
#pragma unroll
        for (int ns = 0; ns < 4; ns++) {
            int row = bm + wm + ms * 16 + (lane >> 2);
            int col = bn + wn + ns * 8 + (lane & 3) * 2;
            if (row < M) {
                float2 o = make_float2(acc[ms][ns][0], acc[ms][ns][1]);
                *(float2*)(C + (size_t)row * 256 + col) = o;
            }
            if (row + 8 < M) {
                float2 o = make_float2(acc[ms][ns][2], acc[ms][ns][3]);
                *(float2*)(C + (size_t)(row + 8) * 256 + col) = o;
            }
        }
    }
}

template <int MODE>
__global__ void __launch_bounds__(256, 2)
gemm_mma(const float* __restrict__ A, const float* __restrict__ nm,
         const unsigned short* __restrict__ Bhi, const unsigned short* __restrict__ Blo,
         float* __restrict__ C, int M)
{
    __shared__ __align__(16) GemmSmem sm;
    gemm_body<MODE>(sm, A, nm, Bhi, Blo, C, M, blockIdx.x * 128, blockIdx.y * 128);
}

// ---------------- fused edge pass: score + exp + den + UNNORMALIZED agg ------
__global__ void edge_fused_kernel(const int* __restrict__ srcIdx,
                                  const int* __restrict__ dstIdx,
                                  const float* __restrict__ emask,
                                  const float* __restrict__ hs,
                                  const float* __restrict__ hd,
                                  const float* __restrict__ a,
                                  float* __restrict__ outp)
{
    int e = (blockIdx.x * blockDim.x + threadIdx.x) >> 5;
    int lane = threadIdx.x & 31;
    if (e >= E_) return;
    int s = srcIdx[e];
    int d = dstIdx[e];
    float em = emask[e];
    const float4* hsp = (const float4*)(hs + (size_t)s * 256) + lane * 2;
    const float4* hdp = (const float4*)(hd + (size_t)d * 256) + lane * 2;
    float4 s0 = __ldg(hsp), s1 = __ldg(hsp + 1);
    float4 d0 = __ldg(hdp), d1 = __ldg(hdp + 1);
    const float4* ap = (const float4*)a + lane * 2;
    float4 a0 = __ldg(ap), a1v = __ldg(ap + 1);

    float v, part = 0.0f;
    v = s0.x + d0.x; v = v > 0.f ? v : 0.2f * v; part = fmaf(a0.x, v, part);
    v = s0.y + d0.y; v = v > 0.f ? v : 0.2f * v; part = fmaf(a0.y, v, part);
    v = s0.z + d0.z; v = v > 0.f ? v : 0.2f * v; part = fmaf(a0.z, v, part);
    v = s0.w + d0.w; v = v > 0.f ? v : 0.2f * v; part = fmaf(a0.w, v, part);
    v = s1.x + d1.x; v = v > 0.f ? v : 0.2f * v; part = fmaf(a1v.x, v, part);
    v = s1.y + d1.y; v = v > 0.f ? v : 0.2f * v; part = fmaf(a1v.y, v, part);
    v = s1.z + d1.z; v = v > 0.f ? v : 0.2f * v; part = fmaf(a1v.z, v, part);
    v = s1.w + d1.w; v = v > 0.f ? v : 0.2f * v; part = fmaf(a1v.w, v, part);

    part += __shfl_xor_sync(0xffffffffu, part, 1);
    part += __shfl_xor_sync(0xffffffffu, part, 2);
    part += __shfl_xor_sync(0xffffffffu, part, 4);

    float p = expf(part);
    if ((lane & 7) == 0)
        atomicAdd(&g_den[(size_t)d * 4 + (lane >> 3)], p);

    float wh = p * em;
    float* op = outp + (size_t)d * 256 + lane * 8;
    redAddV4(op,     wh * s0.x, wh * s0.y, wh * s0.z, wh * s0.w);
    redAddV4(op + 4, wh * s1.x, wh * s1.y, wh * s1.z, wh * s1.w);
}

// ---------------- MMA pool: normalize X -> scores -> softmax -> S^T @ X ------
#define XSTR 264
#define WSTR 72
#define POOL_SMEM (2 * 128 * XSTR * 2 + 2 * 256 * WSTR * 2)

__global__ void __launch_bounds__(256)
pool_mma(const float* __restrict__ X, const float* __restrict__ den,
         const float* __restrict__ Wa)
{
    extern __shared__ __align__(16) char smem[];
    unsigned short* Xh = (unsigned short*)smem;
    unsigned short* Xl = Xh + 128 * XSTR;
    unsigned short* Wh = Xl + 128 * XSTR;
    unsigned short* Wl = Wh + 256 * WSTR;
    unsigned short* Sh = Wh;
    unsigned short* Sl = Wl;

    const int tid = threadIdx.x;
    const int lane = tid & 31;
    const int warp = tid >> 5;
    const int row0 = blockIdx.x * 128;

#pragma unroll
    for (int j = 0; j < 32; j++) {
        int idx = tid + j * 256;
        int r = idx >> 6;
        int c4 = (idx & 63) << 2;
        int grow = row0 + r;
        float4 v = make_float4(0.f, 0.f, 0.f, 0.f);
        if (grow < N_) {
            v = *(const float4*)(X + (size_t)grow * 256 + c4);
            float inv = 1.0f / (den[(size_t)grow * 4 + (c4 >> 6)] + 1e-16f);
            v.x *= inv; v.y *= inv; v.z *= inv; v.w *= inv;
        }
        int base = r * XSTR + c4;
        split1(v.x, &Xh[base + 0], &Xl[base + 0]);
        split1(v.y, &Xh[base + 1], &Xl[base + 1]);
        split1(v.z, &Xh[base + 2], &Xl[base + 2]);
        split1(v.w, &Xh[base + 3], &Xl[base + 3]);
    }
#pragma unroll
    for (int j = 0; j < 16; j++) {
        int idx = tid + j * 256;
        int r = idx >> 4;
        int c4 = (idx & 15) << 2;
        float4 v = *(const float4*)(Wa + (size_t)r * 64 + c4);
        int base = r * WSTR + c4;
        split1(v.x, &Wh[base + 0], &Wl[base + 0]);
        split1(v.y, &Wh[base + 1], &Wl[base + 1]);
        split1(v.z, &Wh[base + 2], &Wl[base + 2]);
        split1(v.w, &Wh[base + 3], &Wl[base + 3]);
    }
    __syncthreads();

    float sc[8][4];
#pragma unroll
    for (int i = 0; i < 8; i++)
#pragma unroll
        for (int r = 0; r < 4; r++) sc[i][r] = 0.0f;

    const int arow = (lane & 7) + ((lane >> 3) & 1) * 8;
#pragma unroll 1
    for (int k = 0; k < 256; k += 16) {
        uint32_t ah[4], al[4];
        int rbase = (warp * 16 + arow) * XSTR + k + (lane >> 4) * 8;
        LDSM4(ah[0], ah[1], ah[2], ah[3], smem_u32(&Xh[rbase]));
        LDSM4(al[0], al[1], al[2], al[3], smem_u32(&Xl[rbase]));
        uint32_t bh[8][2], bl[8][2];
        int brow = k + (lane & 7) + ((lane >> 3) & 1) * 8;
#pragma unroll
        for (int g = 0; g < 4; g++) {
            int c = g * 16 + (lane >> 4) * 8;
            uint32_t r0, r1, r2, r3;
            LDSM4T(r0, r1, r2, r3, smem_u32(&Wh[brow * WSTR + c]));
            bh[g * 2][0] = r0; bh[g * 2][1] = r1;
            bh[g * 2 + 1][0] = r2; bh[g * 2 + 1][1] = r3;
            LDSM4T(r0, r1, r2, r3, smem_u32(&Wl[brow * WSTR + c]));
            bl[g * 2][0] = r0; bl[g * 2][1] = r1;
            bl[g * 2 + 1][0] = r2; bl[g * 2 + 1][1] = r3;
        }
#pragma unroll
        for (int ns = 0; ns < 8; ns++) {
            mma_bf16(sc[ns], ah, bh[ns]);
            mma_bf16(sc[ns], ah, bl[ns]);
            mma_bf16(sc[ns], al, bh[ns]);
        }
    }

    float mA = -1e30f, mB = -1e30f;
#pragma unroll
    for (int ns = 0; ns < 8; ns++) {
        mA = fmaxf(mA, fmaxf(sc[ns][0], sc[ns][1]));
        mB = fmaxf(mB, fmaxf(sc[ns][2], sc[ns][3]));
    }
    mA = fmaxf(mA, __shfl_xor_sync(0xffffffffu, mA, 1));
    mA = fmaxf(mA, __shfl_xor_sync(0xffffffffu, mA, 2));
    mB = fmaxf(mB, __shfl_xor_sync(0xffffffffu, mB, 1));
    mB = fmaxf(mB, __shfl_xor_sync(0xffffffffu, mB, 2));
    float sumA = 0.0f, sumB = 0.0f;
#pragma unroll
    for (int ns = 0; ns < 8; ns++) {
        sc[ns][0] = expf(sc[ns][0] - mA); sc[ns][1] = expf(sc[ns][1] - mA);
        sc[ns][2] = expf(sc[ns][2] - mB); sc[ns][3] = expf(sc[ns][3] - mB);
        sumA += sc[ns][0] + sc[ns][1];
        sumB += sc[ns][2] + sc[ns][3];
    }
    sumA += __shfl_xor_sync(0xffffffffu, sumA, 1);
    sumA += __shfl_xor_sync(0xffffffffu, sumA, 2);
    sumB += __shfl_xor_sync(0xffffffffu, sumB, 1);
    sumB += __shfl_xor_sync(0xffffffffu, sumB, 2);
    float invA = 1.0f / sumA, invB = 1.0f / sumB;

    __syncthreads();

    {
        int rA = warp * 16 + (lane >> 2);
        int rB = rA + 8;
        int colb = (lane & 3) * 2;
#pragma unroll
        for (int ns = 0; ns < 8; ns++) {
            int col = ns * 8 + colb;
            float a0 = sc[ns][0] * invA, a1 = sc[ns][1] * invA;
            float b0 = sc[ns][2] * invB, b1 = sc[ns][3] * invB;
            *(uint32_t*)&Sh[rA * WSTR + col] = pack_bf2(a0, a1);
            *(uint32_t*)&Sl[rA * WSTR + col] = pack_bf2_lo(a0, a1);
            *(uint32_t*)&Sh[rB * WSTR + col] = pack_bf2(b0, b1);
            *(uint32_t*)&Sl[rB * WSTR + col] = pack_bf2_lo(b0, b1);
        }
    }
    __syncthreads();

    float pc[4][4][4];
#pragma unroll
    for (int i = 0; i < 4; i++)
#pragma unroll
        for (int j = 0; j < 4; j++)
#pragma unroll
            for (int r = 0; r < 4; r++) pc[i][j][r] = 0.0f;

    const int nw = warp * 32;
#pragma unroll 1
    for (int kk = 0; kk < 128; kk += 16) {
        uint32_t sah[4][4], sal[4][4];
        int srow = kk + ((lane >> 4) & 1) * 8 + (lane & 7);
        int scoff = ((lane >> 3) & 1) * 8;
#pragma unroll
        for (int mt = 0; mt < 4; mt++) {
            int sc2 = mt * 16 + scoff;
            LDSM4T(sah[mt][0], sah[mt][1], sah[mt][2], sah[mt][3],
                   smem_u32(&Sh[srow * WSTR + sc2]));
            LDSM4T(sal[mt][0], sal[mt][1], sal[mt][2], sal[mt][3],
                   smem_u32(&Sl[srow * WSTR + sc2]));
        }
        uint32_t xbh[4][2], xbl[4][2];
        int brow = kk + (lane & 7) + ((lane >> 3) & 1) * 8;
#pragma unroll
        for (int g = 0; g < 2; g++) {
            int c = nw + g * 16 + (lane >> 4) * 8;
            uint32_t r0, r1, r2, r3;
            LDSM4T(r0, r1, r2, r3, smem_u32(&Xh[brow * XSTR + c]));
            xbh[g * 2][0] = r0; xbh[g * 2][1] = r1;
            xbh[g * 2 + 1][0] = r2; xbh[g * 2 + 1][1] = r3;
            LDSM4T(r0, r1, r2, r3, smem_u32(&Xl[brow * XSTR + c]));
            xbl[g * 2][0] = r0; xbl[g * 2][1] = r1;
            xbl[g * 2 + 1][0] = r2; xbl[g * 2 + 1][1] = r3;
        }
#pragma unroll
        for (int mt = 0; mt < 4; mt++)
#pragma unroll
            for (int ns = 0; ns < 4; ns++) {
                mma_bf16(pc[mt][ns], sah[mt], xbh[ns]);
                mma_bf16(pc[mt][ns], sah[mt], xbl[ns]);
                mma_bf16(pc[mt][ns], sal[mt], xbh[ns]);
            }
    }

#pragma unroll
    for (int mt = 0; mt < 4; mt++)
#pragma unroll
        for (int ns = 0; ns < 4; ns++) {
            int kidx = mt * 16 + (lane >> 2);
            int col = nw + ns * 8 + (lane & 3) * 2;
            redAddV2(&g_pool[(size_t)kidx * 256 + col], pc[mt][ns][0], pc[mt][ns][1]);
            redAddV2(&g_pool[(size_t)(kidx + 8) * 256 + col], pc[mt][ns][2], pc[mt][ns][3]);
        }
}

// ---------------- edge_attr means over all T ---------------------------------
__global__ void edge_sum_kernel(const float* __restrict__ ea)
{
    int t = blockIdx.y;
    const float* p = ea + (size_t)t * E_;
    float s = 0.0f;
    for (int i = blockIdx.x * blockDim.x + threadIdx.x; i < E_; i += gridDim.x * blockDim.x)
        s += p[i];
#pragma unroll
    for (int o = 16; o; o >>= 1) s += __shfl_xor_sync(0xffffffffu, s, o);
    __shared__ float red[8];
    int lane = threadIdx.x & 31, w = threadIdx.x >> 5;
    if (lane == 0) red[w] = s;
    __syncthreads();
    if (threadIdx.x == 0) {
        float bs = 0.0f;
        for (int i = 0; i < (int)(blockDim.x >> 5); i++) bs += red[i];
        atomicAdd(&g_esum[t], bs);
    }
}

// ---------------- final classifier -------------------------------------------
__global__ void final_kernel(const float* __restrict__ Wcls, const float* __restrict__ bcls,
                             float* __restrict__ out)
{
    int k = blockIdx.x;
    int lane = threadIdx.x;
    float s = 0.0f;
    for (int d = lane; d < 256; d += 32) s += g_pool[(size_t)k * 256 + d] * Wcls[d];
#pragma unroll
    for (int o = 16; o; o >>= 1) s += __shfl_xor_sync(0xffffffffu, s, o);
    if (lane == 0) {
        float extra = 0.0f;
#pragma unroll
        for (int t = 0; t < T_; t++) extra += (g_esum[t] * (1.0f / E_)) * Wcls[256 + t];
        float z = s + extra + bcls[0];
        out[k] = 1.0f / (1.0f + expf(-z));
    }
}

// ---------------- launch -------------------------------------------------------
extern "C" void kernel_launch(void* const* d_in, const int* in_sizes, int n_in,
                              void* d_out, int out_size)
{
    const float* x_pkg = (const float*)d_in[0];
    const float* x_dst = (const float*)d_in[1];
    const int*   eidx  = (const int*)d_in[2];
    const float* eattr = (const float*)d_in[3];
    const float* nmask = (const float*)d_in[4];
    const float* emask = (const float*)d_in[5];
    const float* W1s   = (const float*)d_in[6];
    const float* W1d   = (const float*)d_in[7];
    const float* a1    = (const float*)d_in[8];
    const float* W2s   = (const float*)d_in[9];
    const float* W2d   = (const float*)d_in[10];
    const float* a2    = (const float*)d_in[11];
    const float* Was   = (const float*)d_in[12];
    const float* Wcl   = (const float*)d_in[13];
    const float* bcl   = (const float*)d_in[14];
    float* out = (float*)d_out;

    const int tsel = T_ - 1;
    const int* src5 = eidx + (size_t)tsel * 2 * E_;
    const int* dst5 = src5 + E_;
    const float* x_dst5 = x_dst + (size_t)tsel * N_ * D_;
    const float* W1s5 = W1s + (size_t)tsel * D_ * 256;
    const float* W1d5 = W1d + (size_t)tsel * D_ * 256;
    const float* a1_5 = a1 + (size_t)tsel * 256;
    const float* W2s5 = W2s + (size_t)tsel * D_ * 256;
    const float* W2d5 = W2d + (size_t)tsel * D_ * 256;
    const float* a2_5 = a2 + (size_t)tsel * 256;

    float *hs1, *hd1, *hs2, *hd2, *h1, *h2, *den;
    unsigned short *whi, *wlo;
    cudaGetSymbolAddress((void**)&hs1, g_hs1);
    cudaGetSymbolAddress((void**)&hd1, g_hd1);
    cudaGetSymbolAddress((void**)&hs2, g_hs2);
    cudaGetSymbolAddress((void**)&hd2, g_hd2);
    cudaGetSymbolAddress((void**)&h1,  g_h1);
    cudaGetSymbolAddress((void**)&h2,  g_h2);
    cudaGetSymbolAddress((void**)&den, g_den);
    cudaGetSymbolAddress((void**)&whi, g_Whi);
    cudaGetSymbolAddress((void**)&wlo, g_Wlo);

    cudaFuncSetAttribute(pool_mma, cudaFuncAttributeMaxDynamicSharedMemorySize, POOL_SMEM);

    dim3 ggrid(391, 2);
    const int egrid = (E_ + 7) / 8;

    init1_kernel<<<2048, 256>>>();
    // pre-split all 4 weight matrices: slot 0=W1s, 1=W1d, 2=W2s, 3=W2d
    split_w_kernel<<<dim3(256, 4), 256>>>(W1s5, W1d5, W2s5, W2d5);

    gemm_mma<0><<<ggrid, 256>>>(x_pkg,  nmask, whi + 0 * 65536, wlo + 0 * 65536, hs1, N_);
    gemm_mma<0><<<ggrid, 256>>>(x_dst5, nmask, whi + 1 * 65536, wlo + 1 * 65536, hd1, N_);
    gemm_mma<1><<<ggrid, 256>>>(x_pkg,  nullptr, whi + 2 * 65536, wlo + 2 * 65536, hs2, N_);

    // layer 1: fused score+exp+den+unnormalized-agg
    edge_fused_kernel<<<egrid, 256>>>(src5, dst5, emask, hs1, hd1, a1_5, h1);

    // layer-2 dst projection; normalization (den1) + relu folded into A-staging
    gemm_mma<2><<<ggrid, 256>>>(h1, den, whi + 3 * 65536, wlo + 3 * 65536, hd2, N_);

    init2_kernel<<<2048, 256>>>();   // zero h2 + den (after gemm consumed den1)

    // layer 2: fused edge pass
    edge_fused_kernel<<<egrid, 256>>>(src5, dst5, emask, hs2, hd2, a2_5, h2);

    edge_sum_kernel<<<dim3(32, T_), 256>>>(eattr);
    pool_mma<<<391, 256, POOL_SMEM>>>(h2, den, Was);
    final_kernel<<<K_, 32>>>(Wcl, bcl, out);
}

// round 8
// speedup vs baseline: 1.1399x; 1.0673x over previous
#include <cuda_runtime.h>
#include <cuda_bf16.h>
#include <math.h>
#include <stdint.h>

#define N_ 50000
#define D_ 256
#define E_ 250000
#define T_ 6
#define H_ 4
#define K_ 64

// ---------------- scratch (device globals; no runtime allocation) ----------
__device__ float g_hs1[(size_t)N_ * D_];
__device__ float g_hd1[(size_t)N_ * D_];
__device__ float g_hs2[(size_t)N_ * D_];
__device__ float g_hd2[(size_t)N_ * D_];
__device__ float g_h1[(size_t)N_ * D_];
__device__ float g_h2[(size_t)N_ * D_];
__device__ float g_den[2][(size_t)N_ * H_];
__device__ float g_pool[(size_t)K_ * D_];
__device__ float g_esum[T_];
// pre-split weight matrices (bf16 hi/lo), 4 x 256x256
__device__ unsigned short g_Whi[4 * 65536];
__device__ unsigned short g_Wlo[4 * 65536];

// ---------------- helpers ---------------------------------------------------
__device__ __forceinline__ void redAddV4(float* p, float a, float b, float c, float d) {
    asm volatile("red.global.add.v4.f32 [%0], {%1,%2,%3,%4};"
                 :: "l"(p), "f"(a), "f"(b), "f"(c), "f"(d) : "memory");
}
__device__ __forceinline__ void redAddV2(float* p, float a, float b) {
    asm volatile("red.global.add.v2.f32 [%0], {%1,%2};"
                 :: "l"(p), "f"(a), "f"(b) : "memory");
}

__device__ __forceinline__ uint32_t smem_u32(const void* p) {
    return (uint32_t)__cvta_generic_to_shared(p);
}

#define CP_ASYNC16(dst, src) \
    asm volatile("cp.async.cg.shared.global [%0], [%1], 16;" :: "r"(dst), "l"(src))
#define CP_ASYNC16_Z(dst, src, n) \
    asm volatile("cp.async.cg.shared.global [%0], [%1], 16, %2;" :: "r"(dst), "l"(src), "r"(n))
#define CP_COMMIT() asm volatile("cp.async.commit_group;" ::: "memory")
#define CP_WAIT_ALL() asm volatile("cp.async.wait_group 0;" ::: "memory")

#define LDSM4(R0, R1, R2, R3, ADDR) \
    asm volatile("ldmatrix.sync.aligned.m8n8.x4.shared.b16 {%0,%1,%2,%3}, [%4];" \
                 : "=r"(R0), "=r"(R1), "=r"(R2), "=r"(R3) : "r"(ADDR))

#define LDSM4T(R0, R1, R2, R3, ADDR) \
    asm volatile("ldmatrix.sync.aligned.m8n8.x4.trans.shared.b16 {%0,%1,%2,%3}, [%4];" \
                 : "=r"(R0), "=r"(R1), "=r"(R2), "=r"(R3) : "r"(ADDR))

__device__ __forceinline__ void mma_bf16(float* c, const uint32_t* a, const uint32_t* b) {
    asm volatile("mma.sync.aligned.m16n8k16.row.col.f32.bf16.bf16.f32 "
                 "{%0,%1,%2,%3},{%4,%5,%6,%7},{%8,%9},{%0,%1,%2,%3};"
                 : "+f"(c[0]), "+f"(c[1]), "+f"(c[2]), "+f"(c[3])
                 : "r"(a[0]), "r"(a[1]), "r"(a[2]), "r"(a[3]), "r"(b[0]), "r"(b[1]));
}

__device__ __forceinline__ void split1(float x, unsigned short* hi, unsigned short* lo) {
    __nv_bfloat16 h = __float2bfloat16(x);
    *hi = __bfloat16_as_ushort(h);
    float r = x - __bfloat162float(h);
    *lo = __bfloat16_as_ushort(__float2bfloat16(r));
}

__device__ __forceinline__ uint32_t pack_bf2(float a, float b) {
    __nv_bfloat16 ha = __float2bfloat16(a);
    __nv_bfloat16 hb = __float2bfloat16(b);
    return (uint32_t)__bfloat16_as_ushort(ha) | ((uint32_t)__bfloat16_as_ushort(hb) << 16);
}
__device__ __forceinline__ uint32_t pack_bf2_lo(float a, float b) {
    __nv_bfloat16 ha = __float2bfloat16(a);
    __nv_bfloat16 hb = __float2bfloat16(b);
    float ra = a - __bfloat162float(ha);
    float rb = b - __bfloat162float(hb);
    __nv_bfloat16 la = __float2bfloat16(ra);
    __nv_bfloat16 lb = __float2bfloat16(rb);
    return (uint32_t)__bfloat16_as_ushort(la) | ((uint32_t)__bfloat16_as_ushort(lb) << 16);
}

// ---------------- init kernel (everything, once) ------------------------------
__global__ void init_all_kernel() {
    int i = blockIdx.x * blockDim.x + threadIdx.x;
    int st = gridDim.x * blockDim.x;
    for (int j = i; j < N_ * D_; j += st) { g_h1[j] = 0.0f; g_h2[j] = 0.0f; }
    for (int j = i; j < N_ * H_; j += st) { g_den[0][j] = 0.0f; g_den[1][j] = 0.0f; }
    for (int j = i; j < K_ * D_; j += st) g_pool[j] = 0.0f;
    for (int j = i; j < T_; j += st) g_esum[j] = 0.0f;
}

// ---------------- pre-split 4 weight matrices into bf16 hi/lo ----------------
__global__ void split_w_kernel(const float* __restrict__ W0, const float* __restrict__ W1,
                               const float* __restrict__ W2, const float* __restrict__ W3)
{
    int i = blockIdx.x * blockDim.x + threadIdx.x;   // 0..65535
    int w = blockIdx.y;
    const float* Ws = (w == 0) ? W0 : (w == 1) ? W1 : (w == 2) ? W2 : W3;
    split1(Ws[i], &g_Whi[w * 65536 + i], &g_Wlo[w * 65536 + i]);
}

// =============== GEMM: C[M x 256] = f(A)[M x 256] @ B[256 x 256] =============
// MODE 0: f = A * nm[row]
// MODE 1: f = relu(A)
// MODE 2: f = relu(A) / (nm[row*4 + kc/2] + 1e-16)   (deferred GAT softmax norm)
// cp.async double-buffered pipeline; B pre-split bf16 hi/lo.
// dynamic smem layout (bytes):
//   sAf32 [2][128*32] f32 : 0      .. 32768
//   sBhi  [2][32*136] u16 : 32768  .. 50176
//   sBlo  [2][32*136] u16 : 50176  .. 67584
//   sAhi  [128*40]    u16 : 67584  .. 77824
//   sAlo  [128*40]    u16 : 77824  .. 88064
#define GEMM_SMEM 88064

template <int MODE>
__global__ void __launch_bounds__(256, 2)
gemm_mma(const float* __restrict__ A, const float* __restrict__ nm,
         const unsigned short* __restrict__ Bhi, const unsigned short* __restrict__ Blo,
         float* __restrict__ C, int M)
{
    extern __shared__ __align__(16) char dsm[];
    float* sAf = (float*)dsm;                                   // [2][4096]
    unsigned short* sBh = (unsigned short*)(dsm + 32768);       // [2][4352]
    unsigned short* sBl = (unsigned short*)(dsm + 50176);       // [2][4352]
    unsigned short* sAhi = (unsigned short*)(dsm + 67584);      // [5120]
    unsigned short* sAlo = (unsigned short*)(dsm + 77824);      // [5120]

    constexpr int ASTR = 40;
    constexpr int BSTR = 136;
    const int tid = threadIdx.x;
    const int lane = tid & 31;
    const int warp = tid >> 5;
    const int wm = (warp & 1) * 64;
    const int wn = (warp >> 1) * 32;
    const int bm = blockIdx.x * 128;
    const int bn = blockIdx.y * 128;

    float acc[4][4][4];
#pragma unroll
    for (int i = 0; i < 4; i++)
#pragma unroll
        for (int j = 0; j < 4; j++)
#pragma unroll
            for (int r = 0; r < 4; r++) acc[i][j][r] = 0.0f;

    const int arow8 = tid >> 3;          // 0..31
    const int acol = (tid & 7) << 2;     // 0..28 (f32 units)
    // row mask (nm for MODE 0), hoisted
    float nmv[4];
    if (MODE == 0) {
#pragma unroll
        for (int rr = 0; rr < 4; rr++) {
            int grow = bm + arow8 + rr * 32;
            nmv[rr] = (grow < M) ? nm[grow] : 0.0f;
        }
    }

    // ---- async copy issuers ----
    auto issueA = [&](int kc, int b) {
        int k0 = kc * 32;
#pragma unroll
        for (int j = 0; j < 4; j++) {
            int idx = tid + j * 256;
            int r = idx >> 3;
            int c4 = (idx & 7) << 2;
            uint32_t dst = smem_u32(sAf + b * 4096 + r * 32 + c4);
            const float* src = A + (size_t)(bm + r) * 256 + k0 + c4;
            int n = (bm + r < M) ? 16 : 0;
            CP_ASYNC16_Z(dst, src, n);
        }
    };
    auto issueB = [&](int kc, int b) {
        int k0 = kc * 32;
#pragma unroll
        for (int j = 0; j < 2; j++) {
            int idx = tid + j * 256;
            int r = idx >> 4;
            int c8 = (idx & 15) << 3;
            CP_ASYNC16(smem_u32(sBh + b * 4352 + r * BSTR + c8),
                       Bhi + (size_t)(k0 + r) * 256 + bn + c8);
            CP_ASYNC16(smem_u32(sBl + b * 4352 + r * BSTR + c8),
                       Blo + (size_t)(k0 + r) * 256 + bn + c8);
        }
    };

    issueA(0, 0); issueB(0, 0); CP_COMMIT();

#pragma unroll 1
    for (int kc = 0; kc < 8; kc++) {
        const int b = kc & 1;
        CP_WAIT_ALL();
        __syncthreads();                       // chunk kc data visible; bufs b^1 free
        if (kc < 7) { issueA(kc + 1, b ^ 1); issueB(kc + 1, b ^ 1); CP_COMMIT(); }

        // ---- split A f32 tile -> bf16 hi/lo (with MODE transform) ----
#pragma unroll
        for (int rr = 0; rr < 4; rr++) {
            int r = arow8 + rr * 32;
            float4 v = *(const float4*)(sAf + b * 4096 + r * 32 + acol);
            if (MODE == 0) {
                float s = nmv[rr];
                v.x *= s; v.y *= s; v.z *= s; v.w *= s;
            } else if (MODE == 1) {
                v.x = fmaxf(v.x, 0.f); v.y = fmaxf(v.y, 0.f);
                v.z = fmaxf(v.z, 0.f); v.w = fmaxf(v.w, 0.f);
            } else {
                int grow = bm + r;
                float inv = 0.0f;
                if (grow < M) inv = 1.0f / (nm[(size_t)grow * 4 + (kc >> 1)] + 1e-16f);
                v.x = fmaxf(v.x, 0.f) * inv; v.y = fmaxf(v.y, 0.f) * inv;
                v.z = fmaxf(v.z, 0.f) * inv; v.w = fmaxf(v.w, 0.f) * inv;
            }
            int base = r * ASTR + acol;
            split1(v.x, &sAhi[base + 0], &sAlo[base + 0]);
            split1(v.y, &sAhi[base + 1], &sAlo[base + 1]);
            split1(v.z, &sAhi[base + 2], &sAlo[base + 2]);
            split1(v.w, &sAhi[base + 3], &sAlo[base + 3]);
        }
        __syncthreads();                       // bf16 A tile ready

        // ---- MMAs (overlapped with in-flight copies of chunk kc+1) ----
        const unsigned short* bh_base = sBh + b * 4352;
        const unsigned short* bl_base = sBl + b * 4352;
#pragma unroll
        for (int kk = 0; kk < 32; kk += 16) {
            uint32_t ah[4][4], al[4][4], bh[4][2], bl[4][2];
            const int ar = (lane & 7) + ((lane >> 3) & 1) * 8;
            const int ac = kk + (lane >> 4) * 8;
#pragma unroll
            for (int ms = 0; ms < 4; ms++) {
                int r = wm + ms * 16 + ar;
                LDSM4(ah[ms][0], ah[ms][1], ah[ms][2], ah[ms][3],
                      smem_u32(&sAhi[r * ASTR + ac]));
                LDSM4(al[ms][0], al[ms][1], al[ms][2], al[ms][3],
                      smem_u32(&sAlo[r * ASTR + ac]));
            }
            const int brow = kk + (lane & 7) + ((lane >> 3) & 1) * 8;
#pragma unroll
            for (int g = 0; g < 2; g++) {
                int c = wn + g * 16 + (lane >> 4) * 8;
                uint32_t r0, r1, r2, r3;
                LDSM4T(r0, r1, r2, r3, smem_u32(&bh_base[brow * BSTR + c]));
                bh[g * 2][0] = r0; bh[g * 2][1] = r1;
                bh[g * 2 + 1][0] = r2; bh[g * 2 + 1][1] = r3;
                LDSM4T(r0, r1, r2, r3, smem_u32(&bl_base[brow * BSTR + c]));
                bl[g * 2][0] = r0; bl[g * 2][1] = r1;
                bl[g * 2 + 1][0] = r2; bl[g * 2 + 1][1] = r3;
            }
#pragma unroll
            for (int ms = 0; ms < 4; ms++)
#pragma unroll
                for (int ns = 0; ns < 4; ns++) {
                    mma_bf16(acc[ms][ns], ah[ms], bh[ns]);
                    mma_bf16(acc[ms][ns], ah[ms], bl[ns]);
                    mma_bf16(acc[ms][ns], al[ms], bh[ns]);
                }
        }
    }

#pragma unroll
    for (int ms = 0; ms < 4; ms++) {
#pragma unroll
        for (int ns = 0; ns < 4; ns++) {
            int row = bm + wm + ms * 16 + (lane >> 2);
            int col = bn + wn + ns * 8 + (lane & 3) * 2;
            if (row < M) {
                float2 o = make_float2(acc[ms][ns][0], acc[ms][ns][1]);
                *(float2*)(C + (size_t)row * 256 + col) = o;
            }
            if (row + 8 < M) {
                float2 o = make_float2(acc[ms][ns][2], acc[ms][ns][3]);
                *(float2*)(C + (size_t)(row + 8) * 256 + col) = o;
            }
        }
    }
}

// ---------------- fused edge pass: score + exp + den + UNNORMALIZED agg ------
__global__ void edge_fused_kernel(const int* __restrict__ srcIdx,
                                  const int* __restrict__ dstIdx,
                                  const float* __restrict__ emask,
                                  const float* __restrict__ hs,
                                  const float* __restrict__ hd,
                                  const float* __restrict__ a,
                                  float* __restrict__ den,
                                  float* __restrict__ outp)
{
    int e = (blockIdx.x * blockDim.x + threadIdx.x) >> 5;
    int lane = threadIdx.x & 31;
    if (e >= E_) return;
    int s = srcIdx[e];
    int d = dstIdx[e];
    float em = emask[e];
    const float4* hsp = (const float4*)(hs + (size_t)s * 256) + lane * 2;
    const float4* hdp = (const float4*)(hd + (size_t)d * 256) + lane * 2;
    float4 s0 = __ldg(hsp), s1 = __ldg(hsp + 1);
    float4 d0 = __ldg(hdp), d1 = __ldg(hdp + 1);
    const float4* ap = (const float4*)a + lane * 2;
    float4 a0 = __ldg(ap), a1v = __ldg(ap + 1);

    float v, part = 0.0f;
    v = s0.x + d0.x; v = v > 0.f ? v : 0.2f * v; part = fmaf(a0.x, v, part);
    v = s0.y + d0.y; v = v > 0.f ? v : 0.2f * v; part = fmaf(a0.y, v, part);
    v = s0.z + d0.z; v = v > 0.f ? v : 0.2f * v; part = fmaf(a0.z, v, part);
    v = s0.w + d0.w; v = v > 0.f ? v : 0.2f * v; part = fmaf(a0.w, v, part);
    v = s1.x + d1.x; v = v > 0.f ? v : 0.2f * v; part = fmaf(a1v.x, v, part);
    v = s1.y + d1.y; v = v > 0.f ? v : 0.2f * v; part = fmaf(a1v.y, v, part);
    v = s1.z + d1.z; v = v > 0.f ? v : 0.2f * v; part = fmaf(a1v.z, v, part);
    v = s1.w + d1.w; v = v > 0.f ? v : 0.2f * v; part = fmaf(a1v.w, v, part);

    part += __shfl_xor_sync(0xffffffffu, part, 1);
    part += __shfl_xor_sync(0xffffffffu, part, 2);
    part += __shfl_xor_sync(0xffffffffu, part, 4);

    float p = expf(part);
    if ((lane & 7) == 0)
        atomicAdd(&den[(size_t)d * 4 + (lane >> 3)], p);

    float wh = p * em;
    float* op = outp + (size_t)d * 256 + lane * 8;
    redAddV4(op,     wh * s0.x, wh * s0.y, wh * s0.z, wh * s0.w);
    redAddV4(op + 4, wh * s1.x, wh * s1.y, wh * s1.z, wh * s1.w);
}

// ---------------- MMA pool: normalize X -> scores -> softmax -> S^T @ X ------
#define XSTR 264
#define WSTR 72
#define POOL_SMEM (2 * 128 * XSTR * 2 + 2 * 256 * WSTR * 2)

__global__ void __launch_bounds__(256)
pool_mma(const float* __restrict__ X, const float* __restrict__ den,
         const float* __restrict__ Wa)
{
    extern __shared__ __align__(16) char smem[];
    unsigned short* Xh = (unsigned short*)smem;
    unsigned short* Xl = Xh + 128 * XSTR;
    unsigned short* Wh = Xl + 128 * XSTR;
    unsigned short* Wl = Wh + 256 * WSTR;
    unsigned short* Sh = Wh;
    unsigned short* Sl = Wl;

    const int tid = threadIdx.x;
    const int lane = tid & 31;
    const int warp = tid >> 5;
    const int row0 = blockIdx.x * 128;

#pragma unroll
    for (int j = 0; j < 32; j++) {
        int idx = tid + j * 256;
        int r = idx >> 6;
        int c4 = (idx & 63) << 2;
        int grow = row0 + r;
        float4 v = make_float4(0.f, 0.f, 0.f, 0.f);
        if (grow < N_) {
            v = *(const float4*)(X + (size_t)grow * 256 + c4);
            float inv = 1.0f / (den[(size_t)grow * 4 + (c4 >> 6)] + 1e-16f);
            v.x *= inv; v.y *= inv; v.z *= inv; v.w *= inv;
        }
        int base = r * XSTR + c4;
        split1(v.x, &Xh[base + 0], &Xl[base + 0]);
        split1(v.y, &Xh[base + 1], &Xl[base + 1]);
        split1(v.z, &Xh[base + 2], &Xl[base + 2]);
        split1(v.w, &Xh[base + 3], &Xl[base + 3]);
    }
#pragma unroll
    for (int j = 0; j < 16; j++) {
        int idx = tid + j * 256;
        int r = idx >> 4;
        int c4 = (idx & 15) << 2;
        float4 v = *(const float4*)(Wa + (size_t)r * 64 + c4);
        int base = r * WSTR + c4;
        split1(v.x, &Wh[base + 0], &Wl[base + 0]);
        split1(v.y, &Wh[base + 1], &Wl[base + 1]);
        split1(v.z, &Wh[base + 2], &Wl[base + 2]);
        split1(v.w, &Wh[base + 3], &Wl[base + 3]);
    }
    __syncthreads();

    float sc[8][4];
#pragma unroll
    for (int i = 0; i < 8; i++)
#pragma unroll
        for (int r = 0; r < 4; r++) sc[i][r] = 0.0f;

    const int arow = (lane & 7) + ((lane >> 3) & 1) * 8;
#pragma unroll 1
    for (int k = 0; k < 256; k += 16) {
        uint32_t ah[4], al[4];
        int rbase = (warp * 16 + arow) * XSTR + k + (lane >> 4) * 8;
        LDSM4(ah[0], ah[1], ah[2], ah[3], smem_u32(&Xh[rbase]));
        LDSM4(al[0], al[1], al[2], al[3], smem_u32(&Xl[rbase]));
        uint32_t bh[8][2], bl[8][2];
        int brow = k + (lane & 7) + ((lane >> 3) & 1) * 8;
#pragma unroll
        for (int g = 0; g < 4; g++) {
            int c = g * 16 + (lane >> 4) * 8;
            uint32_t r0, r1, r2, r3;
            LDSM4T(r0, r1, r2, r3, smem_u32(&Wh[brow * WSTR + c]));
            bh[g * 2][0] = r0; bh[g * 2][1] = r1;
            bh[g * 2 + 1][0] = r2; bh[g * 2 + 1][1] = r3;
            LDSM4T(r0, r1, r2, r3, smem_u32(&Wl[brow * WSTR + c]));
            bl[g * 2][0] = r0; bl[g * 2][1] = r1;
            bl[g * 2 + 1][0] = r2; bl[g * 2 + 1][1] = r3;
        }
#pragma unroll
        for (int ns = 0; ns < 8; ns++) {
            mma_bf16(sc[ns], ah, bh[ns]);
            mma_bf16(sc[ns], ah, bl[ns]);
            mma_bf16(sc[ns], al, bh[ns]);
        }
    }

    float mA = -1e30f, mB = -1e30f;
#pragma unroll
    for (int ns = 0; ns < 8; ns++) {
        mA = fmaxf(mA, fmaxf(sc[ns][0], sc[ns][1]));
        mB = fmaxf(mB, fmaxf(sc[ns][2], sc[ns][3]));
    }
    mA = fmaxf(mA, __shfl_xor_sync(0xffffffffu, mA, 1));
    mA = fmaxf(mA, __shfl_xor_sync(0xffffffffu, mA, 2));
    mB = fmaxf(mB, __shfl_xor_sync(0xffffffffu, mB, 1));
    mB = fmaxf(mB, __shfl_xor_sync(0xffffffffu, mB, 2));
    float sumA = 0.0f, sumB = 0.0f;
#pragma unroll
    for (int ns = 0; ns < 8; ns++) {
        sc[ns][0] = expf(sc[ns][0] - mA); sc[ns][1] = expf(sc[ns][1] - mA);
        sc[ns][2] = expf(sc[ns][2] - mB); sc[ns][3] = expf(sc[ns][3] - mB);
        sumA += sc[ns][0] + sc[ns][1];
        sumB += sc[ns][2] + sc[ns][3];
    }
    sumA += __shfl_xor_sync(0xffffffffu, sumA, 1);
    sumA += __shfl_xor_sync(0xffffffffu, sumA, 2);
    sumB += __shfl_xor_sync(0xffffffffu, sumB, 1);
    sumB += __shfl_xor_sync(0xffffffffu, sumB, 2);
    float invA = 1.0f / sumA, invB = 1.0f / sumB;

    __syncthreads();

    {
        int rA = warp * 16 + (lane >> 2);
        int rB = rA + 8;
        int colb = (lane & 3) * 2;
#pragma unroll
        for (int ns = 0; ns < 8; ns++) {
            int col = ns * 8 + colb;
            float a0 = sc[ns][0] * invA, a1 = sc[ns][1] * invA;
            float b0 = sc[ns][2] * invB, b1 = sc[ns][3] * invB;
            *(uint32_t*)&Sh[rA * WSTR + col] = pack_bf2(a0, a1);
            *(uint32_t*)&Sl[rA * WSTR + col] = pack_bf2_lo(a0, a1);
            *(uint32_t*)&Sh[rB * WSTR + col] = pack_bf2(b0, b1);
            *(uint32_t*)&Sl[rB * WSTR + col] = pack_bf2_lo(b0, b1);
        }
    }
    __syncthreads();

    float pc[4][4][4];
#pragma unroll
    for (int i = 0; i < 4; i++)
#pragma unroll
        for (int j = 0; j < 4; j++)
#pragma unroll
            for (int r = 0; r < 4; r++) pc[i][j][r] = 0.0f;

    const int nw = warp * 32;
#pragma unroll 1
    for (int kk = 0; kk < 128; kk += 16) {
        uint32_t sah[4][4], sal[4][4];
        int srow = kk + ((lane >> 4) & 1) * 8 + (lane & 7);
        int scoff = ((lane >> 3) & 1) * 8;
#pragma unroll
        for (int mt = 0; mt < 4; mt++) {
            int sc2 = mt * 16 + scoff;
            LDSM4T(sah[mt][0], sah[mt][1], sah[mt][2], sah[mt][3],
                   smem_u32(&Sh[srow * WSTR + sc2]));
            LDSM4T(sal[mt][0], sal[mt][1], sal[mt][2], sal[mt][3],
                   smem_u32(&Sl[srow * WSTR + sc2]));
        }
        uint32_t xbh[4][2], xbl[4][2];
        int brow = kk + (lane & 7) + ((lane >> 3) & 1) * 8;
#pragma unroll
        for (int g = 0; g < 2; g++) {
            int c = nw + g * 16 + (lane >> 4) * 8;
            uint32_t r0, r1, r2, r3;
            LDSM4T(r0, r1, r2, r3, smem_u32(&Xh[brow * XSTR + c]));
            xbh[g * 2][0] = r0; xbh[g * 2][1] = r1;
            xbh[g * 2 + 1][0] = r2; xbh[g * 2 + 1][1] = r3;
            LDSM4T(r0, r1, r2, r3, smem_u32(&Xl[brow * XSTR + c]));
            xbl[g * 2][0] = r0; xbl[g * 2][1] = r1;
            xbl[g * 2 + 1][0] = r2; xbl[g * 2 + 1][1] = r3;
        }
#pragma unroll
        for (int mt = 0; mt < 4; mt++)
#pragma unroll
            for (int ns = 0; ns < 4; ns++) {
                mma_bf16(pc[mt][ns], sah[mt], xbh[ns]);
                mma_bf16(pc[mt][ns], sah[mt], xbl[ns]);
                mma_bf16(pc[mt][ns], sal[mt], xbh[ns]);
            }
    }

#pragma unroll
    for (int mt = 0; mt < 4; mt++)
#pragma unroll
        for (int ns = 0; ns < 4; ns++) {
            int kidx = mt * 16 + (lane >> 2);
            int col = nw + ns * 8 + (lane & 3) * 2;
            redAddV2(&g_pool[(size_t)kidx * 256 + col], pc[mt][ns][0], pc[mt][ns][1]);
            redAddV2(&g_pool[(size_t)(kidx + 8) * 256 + col], pc[mt][ns][2], pc[mt][ns][3]);
        }
}

// ---------------- edge_attr means over all T ---------------------------------
__global__ void edge_sum_kernel(const float* __restrict__ ea)
{
    int t = blockIdx.y;
    const float* p = ea + (size_t)t * E_;
    float s = 0.0f;
    for (int i = blockIdx.x * blockDim.x + threadIdx.x; i < E_; i += gridDim.x * blockDim.x)
        s += p[i];
#pragma unroll
    for (int o = 16; o; o >>= 1) s += __shfl_xor_sync(0xffffffffu, s, o);
    __shared__ float red[8];
    int lane = threadIdx.x & 31, w = threadIdx.x >> 5;
    if (lane == 0) red[w] = s;
    __syncthreads();
    if (threadIdx.x == 0) {
        float bs = 0.0f;
        for (int i = 0; i < (int)(blockDim.x >> 5); i++) bs += red[i];
        atomicAdd(&g_esum[t], bs);
    }
}

// ---------------- final classifier -------------------------------------------
__global__ void final_kernel(const float* __restrict__ Wcls, const float* __restrict__ bcls,
                             float* __restrict__ out)
{
    int k = blockIdx.x;
    int lane = threadIdx.x;
    float s = 0.0f;
    for (int d = lane; d < 256; d += 32) s += g_pool[(size_t)k * 256 + d] * Wcls[d];
#pragma unroll
    for (int o = 16; o; o >>= 1) s += __shfl_xor_sync(0xffffffffu, s, o);
    if (lane == 0) {
        float extra = 0.0f;
#pragma unroll
        for (int t = 0; t < T_; t++) extra += (g_esum[t] * (1.0f / E_)) * Wcls[256 + t];
        float z = s + extra + bcls[0];
        out[k] = 1.0f / (1.0f + expf(-z));
    }
}

// ---------------- launch -------------------------------------------------------
extern "C" void kernel_launch(void* const* d_in, const int* in_sizes, int n_in,
                              void* d_out, int out_size)
{
    const float* x_pkg = (const float*)d_in[0];
    const float* x_dst = (const float*)d_in[1];
    const int*   eidx  = (const int*)d_in[2];
    const float* eattr = (const float*)d_in[3];
    const float* nmask = (const float*)d_in[4];
    const float* emask = (const float*)d_in[5];
    const float* W1s   = (const float*)d_in[6];
    const float* W1d   = (const float*)d_in[7];
    const float* a1    = (const float*)d_in[8];
    const float* W2s   = (const float*)d_in[9];
    const float* W2d   = (const float*)d_in[10];
    const float* a2    = (const float*)d_in[11];
    const float* Was   = (const float*)d_in[12];
    const float* Wcl   = (const float*)d_in[13];
    const float* bcl   = (const float*)d_in[14];
    float* out = (float*)d_out;

    const int tsel = T_ - 1;
    const int* src5 = eidx + (size_t)tsel * 2 * E_;
    const int* dst5 = src5 + E_;
    const float* x_dst5 = x_dst + (size_t)tsel * N_ * D_;
    const float* W1s5 = W1s + (size_t)tsel * D_ * 256;
    const float* W1d5 = W1d + (size_t)tsel * D_ * 256;
    const float* a1_5 = a1 + (size_t)tsel * 256;
    const float* W2s5 = W2s + (size_t)tsel * D_ * 256;
    const float* W2d5 = W2d + (size_t)tsel * D_ * 256;
    const float* a2_5 = a2 + (size_t)tsel * 256;

    float *hs1, *hd1, *hs2, *hd2, *h1, *h2, *den;
    unsigned short *whi, *wlo;
    cudaGetSymbolAddress((void**)&hs1, g_hs1);
    cudaGetSymbolAddress((void**)&hd1, g_hd1);
    cudaGetSymbolAddress((void**)&hs2, g_hs2);
    cudaGetSymbolAddress((void**)&hd2, g_hd2);
    cudaGetSymbolAddress((void**)&h1,  g_h1);
    cudaGetSymbolAddress((void**)&h2,  g_h2);
    cudaGetSymbolAddress((void**)&den, g_den);
    cudaGetSymbolAddress((void**)&whi, g_Whi);
    cudaGetSymbolAddress((void**)&wlo, g_Wlo);
    float* den0 = den;
    float* den1 = den + (size_t)N_ * H_;

    cudaFuncSetAttribute(pool_mma, cudaFuncAttributeMaxDynamicSharedMemorySize, POOL_SMEM);
    cudaFuncSetAttribute(gemm_mma<0>, cudaFuncAttributeMaxDynamicSharedMemorySize, GEMM_SMEM);
    cudaFuncSetAttribute(gemm_mma<1>, cudaFuncAttributeMaxDynamicSharedMemorySize, GEMM_SMEM);
    cudaFuncSetAttribute(gemm_mma<2>, cudaFuncAttributeMaxDynamicSharedMemorySize, GEMM_SMEM);

    dim3 ggrid(391, 2);
    const int egrid = (E_ + 7) / 8;

    init_all_kernel<<<2048, 256>>>();
    split_w_kernel<<<dim3(256, 4), 256>>>(W1s5, W1d5, W2s5, W2d5);

    gemm_mma<0><<<ggrid, 256, GEMM_SMEM>>>(x_pkg,  nmask, whi + 0 * 65536, wlo + 0 * 65536, hs1, N_);
    gemm_mma<0><<<ggrid, 256, GEMM_SMEM>>>(x_dst5, nmask, whi + 1 * 65536, wlo + 1 * 65536, hd1, N_);
    gemm_mma<1><<<ggrid, 256, GEMM_SMEM>>>(x_pkg,  nullptr, whi + 2 * 65536, wlo + 2 * 65536, hs2, N_);

    // layer 1: fused score+exp+den+unnormalized-agg
    edge_fused_kernel<<<egrid, 256>>>(src5, dst5, emask, hs1, hd1, a1_5, den0, h1);

    // layer-2 dst projection; normalization (den0) + relu folded into A-staging
    gemm_mma<2><<<ggrid, 256, GEMM_SMEM>>>(h1, den0, whi + 3 * 65536, wlo + 3 * 65536, hd2, N_);

    // layer 2: fused edge pass (h2/den1 pre-zeroed in init_all)
    edge_fused_kernel<<<egrid, 256>>>(src5, dst5, emask, hs2, hd2, a2_5, den1, h2);

    edge_sum_kernel<<<dim3(32, T_), 256>>>(eattr);
    pool_mma<<<391, 256, POOL_SMEM>>>(h2, den1, Was);
    final_kernel<<<K_, 32>>>(Wcl, bcl, out);
}

// round 10
// speedup vs baseline: 1.3753x; 1.2065x over previous
#include <cuda_runtime.h>
#include <cuda_bf16.h>
#include <math.h>
#include <stdint.h>

#define N_ 50000
#define D_ 256
#define E_ 250000
#define T_ 6
#define H_ 4
#define K_ 64
#define SCAN_B 196   // ceil(N_/256)

// ---------------- scratch (device globals; no runtime allocation) ----------
__device__ float g_hs1[(size_t)N_ * D_];
__device__ float g_hd1[(size_t)N_ * D_];
__device__ float g_hs2[(size_t)N_ * D_];
__device__ float g_hd2[(size_t)N_ * D_];
__device__ float g_h1[(size_t)N_ * D_];
__device__ float g_h2[(size_t)N_ * D_];
__device__ float g_pool[(size_t)K_ * D_];
__device__ float g_esum[T_];
// pre-split weight matrices (bf16 hi/lo), 4 x 256x256 row-major [K,N]
__device__ unsigned short g_Whi[4 * 65536];
__device__ unsigned short g_Wlo[4 * 65536];
// CSR (dst-grouped edge list), rebuilt every launch
__device__ int g_deg[N_];
__device__ int g_rowptr[N_];
__device__ int g_cursor[N_];     // after scatter: rowend
__device__ int g_blocksum[256];
__device__ int g_eid[E_];

// ---------------- helpers ---------------------------------------------------
__device__ __forceinline__ void redAddV2(float* p, float a, float b) {
    asm volatile("red.global.add.v2.f32 [%0], {%1,%2};"
                 :: "l"(p), "f"(a), "f"(b) : "memory");
}

__device__ __forceinline__ uint32_t smem_u32(const void* p) {
    return (uint32_t)__cvta_generic_to_shared(p);
}

#define CP_ASYNC16(dst, src) \
    asm volatile("cp.async.cg.shared.global [%0], [%1], 16;" :: "r"(dst), "l"(src))
#define CP_ASYNC16_Z(dst, src, n) \
    asm volatile("cp.async.cg.shared.global [%0], [%1], 16, %2;" :: "r"(dst), "l"(src), "r"(n))
#define CP_COMMIT() asm volatile("cp.async.commit_group;" ::: "memory")
#define CP_WAIT_ALL() asm volatile("cp.async.wait_group 0;" ::: "memory")

#define LDSM4(R0, R1, R2, R3, ADDR) \
    asm volatile("ldmatrix.sync.aligned.m8n8.x4.shared.b16 {%0,%1,%2,%3}, [%4];" \
                 : "=r"(R0), "=r"(R1), "=r"(R2), "=r"(R3) : "r"(ADDR))

#define LDSM4T(R0, R1, R2, R3, ADDR) \
    asm volatile("ldmatrix.sync.aligned.m8n8.x4.trans.shared.b16 {%0,%1,%2,%3}, [%4];" \
                 : "=r"(R0), "=r"(R1), "=r"(R2), "=r"(R3) : "r"(ADDR))

__device__ __forceinline__ void mma_bf16(float* c, const uint32_t* a, const uint32_t* b) {
    asm volatile("mma.sync.aligned.m16n8k16.row.col.f32.bf16.bf16.f32 "
                 "{%0,%1,%2,%3},{%4,%5,%6,%7},{%8,%9},{%0,%1,%2,%3};"
                 : "+f"(c[0]), "+f"(c[1]), "+f"(c[2]), "+f"(c[3])
                 : "r"(a[0]), "r"(a[1]), "r"(a[2]), "r"(a[3]), "r"(b[0]), "r"(b[1]));
}

__device__ __forceinline__ void split1(float x, unsigned short* hi, unsigned short* lo) {
    __nv_bfloat16 h = __float2bfloat16(x);
    *hi = __bfloat16_as_ushort(h);
    float r = x - __bfloat162float(h);
    *lo = __bfloat16_as_ushort(__float2bfloat16(r));
}

__device__ __forceinline__ uint32_t pack_bf2(float a, float b) {
    __nv_bfloat16 ha = __float2bfloat16(a);
    __nv_bfloat16 hb = __float2bfloat16(b);
    return (uint32_t)__bfloat16_as_ushort(ha) | ((uint32_t)__bfloat16_as_ushort(hb) << 16);
}
__device__ __forceinline__ uint32_t pack_bf2_lo(float a, float b) {
    __nv_bfloat16 ha = __float2bfloat16(a);
    __nv_bfloat16 hb = __float2bfloat16(b);
    float ra = a - __bfloat162float(ha);
    float rb = b - __bfloat162float(hb);
    return (uint32_t)__bfloat16_as_ushort(__float2bfloat16(ra)) |
           ((uint32_t)__bfloat16_as_ushort(__float2bfloat16(rb)) << 16);
}

// ---------------- init kernel -------------------------------------------------
__global__ void init_kernel() {
    int i = blockIdx.x * blockDim.x + threadIdx.x;
    int st = gridDim.x * blockDim.x;
    for (int j = i; j < N_; j += st) g_deg[j] = 0;
    for (int j = i; j < K_ * D_; j += st) g_pool[j] = 0.0f;
    for (int j = i; j < T_; j += st) g_esum[j] = 0.0f;
}

// ---------------- pre-split 4 weight matrices into bf16 hi/lo ----------------
__global__ void split_w_kernel(const float* __restrict__ W0, const float* __restrict__ W1,
                               const float* __restrict__ W2, const float* __restrict__ W3)
{
    int i = blockIdx.x * blockDim.x + threadIdx.x;
    int w = blockIdx.y;
    const float* Ws = (w == 0) ? W0 : (w == 1) ? W1 : (w == 2) ? W2 : W3;
    split1(Ws[i], &g_Whi[w * 65536 + i], &g_Wlo[w * 65536 + i]);
}

// ---------------- CSR build ----------------------------------------------------
__global__ void hist_kernel(const int* __restrict__ dst) {
    int e = blockIdx.x * blockDim.x + threadIdx.x;
    if (e < E_) atomicAdd(&g_deg[dst[e]], 1);
}

__global__ void scanA_kernel() {
    __shared__ int sm[256];
    int t = threadIdx.x;
    int i = blockIdx.x * 256 + t;
    int v = (i < N_) ? g_deg[i] : 0;
    sm[t] = v;
    __syncthreads();
#pragma unroll
    for (int off = 1; off < 256; off <<= 1) {
        int x = (t >= off) ? sm[t - off] : 0;
        __syncthreads();
        sm[t] += x;
        __syncthreads();
    }
    if (i < N_) g_rowptr[i] = sm[t] - v;             // exclusive within block
    if (t == 255) g_blocksum[blockIdx.x] = sm[255];  // block total
}

__global__ void scanB_kernel() {
    __shared__ int sm[256];
    int t = threadIdx.x;
    int v = (t < SCAN_B) ? g_blocksum[t] : 0;
    sm[t] = v;
    __syncthreads();
#pragma unroll
    for (int off = 1; off < 256; off <<= 1) {
        int x = (t >= off) ? sm[t - off] : 0;
        __syncthreads();
        sm[t] += x;
        __syncthreads();
    }
    g_blocksum[t] = sm[t] - v;                        // exclusive block offsets
}

__global__ void scanC_kernel() {
    int i = blockIdx.x * 256 + threadIdx.x;
    if (i < N_) {
        int r = g_rowptr[i] + g_blocksum[blockIdx.x];
        g_rowptr[i] = r;
        g_cursor[i] = r;
    }
}

__global__ void scatter_kernel(const int* __restrict__ dst) {
    int e = blockIdx.x * blockDim.x + threadIdx.x;
    if (e < E_) {
        int pos = atomicAdd(&g_cursor[dst[e]], 1);
        g_eid[pos] = e;
    }
}

// =============== GEMM (R8, proven): C[M x 256] = f(A)[M x 256] @ B[256 x 256]
// MODE 0: f = A * nm[row];  MODE 1: f = relu(A)
#define GEMM_SMEM 88064

template <int MODE>
__global__ void __launch_bounds__(256, 2)
gemm_mma(const float* __restrict__ A, const float* __restrict__ nm,
         const unsigned short* __restrict__ Bhi, const unsigned short* __restrict__ Blo,
         float* __restrict__ C, int M)
{
    extern __shared__ __align__(16) char dsm[];
    float* sAf = (float*)dsm;                                   // [2][4096]
    unsigned short* sBh = (unsigned short*)(dsm + 32768);       // [2][4352]
    unsigned short* sBl = (unsigned short*)(dsm + 50176);       // [2][4352]
    unsigned short* sAhi = (unsigned short*)(dsm + 67584);      // [5120]
    unsigned short* sAlo = (unsigned short*)(dsm + 77824);      // [5120]

    constexpr int ASTR = 40;
    constexpr int BSTR = 136;
    const int tid = threadIdx.x;
    const int lane = tid & 31;
    const int warp = tid >> 5;
    const int wm = (warp & 1) * 64;
    const int wn = (warp >> 1) * 32;
    const int bm = blockIdx.x * 128;
    const int bn = blockIdx.y * 128;

    float acc[4][4][4];
#pragma unroll
    for (int i = 0; i < 4; i++)
#pragma unroll
        for (int j = 0; j < 4; j++)
#pragma unroll
            for (int r = 0; r < 4; r++) acc[i][j][r] = 0.0f;

    const int arow8 = tid >> 3;
    const int acol = (tid & 7) << 2;
    float nmv[4];
    if (MODE == 0) {
#pragma unroll
        for (int rr = 0; rr < 4; rr++) {
            int grow = bm + arow8 + rr * 32;
            nmv[rr] = (grow < M) ? nm[grow] : 0.0f;
        }
    }

    auto issueA = [&](int kc, int b) {
        int k0 = kc * 32;
#pragma unroll
        for (int j = 0; j < 4; j++) {
            int idx = tid + j * 256;
            int r = idx >> 3;
            int c4 = (idx & 7) << 2;
            uint32_t dst = smem_u32(sAf + b * 4096 + r * 32 + c4);
            const float* src = A + (size_t)(bm + r) * 256 + k0 + c4;
            int n = (bm + r < M) ? 16 : 0;
            CP_ASYNC16_Z(dst, src, n);
        }
    };
    auto issueB = [&](int kc, int b) {
        int k0 = kc * 32;
#pragma unroll
        for (int j = 0; j < 2; j++) {
            int idx = tid + j * 256;
            int r = idx >> 4;
            int c8 = (idx & 15) << 3;
            CP_ASYNC16(smem_u32(sBh + b * 4352 + r * BSTR + c8),
                       Bhi + (size_t)(k0 + r) * 256 + bn + c8);
            CP_ASYNC16(smem_u32(sBl + b * 4352 + r * BSTR + c8),
                       Blo + (size_t)(k0 + r) * 256 + bn + c8);
        }
    };

    issueA(0, 0); issueB(0, 0); CP_COMMIT();

#pragma unroll 1
    for (int kc = 0; kc < 8; kc++) {
        const int b = kc & 1;
        CP_WAIT_ALL();
        __syncthreads();
        if (kc < 7) { issueA(kc + 1, b ^ 1); issueB(kc + 1, b ^ 1); CP_COMMIT(); }

#pragma unroll
        for (int rr = 0; rr < 4; rr++) {
            int r = arow8 + rr * 32;
            float4 v = *(const float4*)(sAf + b * 4096 + r * 32 + acol);
            if (MODE == 0) {
                float s = nmv[rr];
                v.x *= s; v.y *= s; v.z *= s; v.w *= s;
            } else {
                v.x = fmaxf(v.x, 0.f); v.y = fmaxf(v.y, 0.f);
                v.z = fmaxf(v.z, 0.f); v.w = fmaxf(v.w, 0.f);
            }
            int base = r * ASTR + acol;
            split1(v.x, &sAhi[base + 0], &sAlo[base + 0]);
            split1(v.y, &sAhi[base + 1], &sAlo[base + 1]);
            split1(v.z, &sAhi[base + 2], &sAlo[base + 2]);
            split1(v.w, &sAhi[base + 3], &sAlo[base + 3]);
        }
        __syncthreads();

        const unsigned short* bh_base = sBh + b * 4352;
        const unsigned short* bl_base = sBl + b * 4352;
#pragma unroll
        for (int kk = 0; kk < 32; kk += 16) {
            uint32_t ah[4][4], al[4][4], bh[4][2], bl[4][2];
            const int ar = (lane & 7) + ((lane >> 3) & 1) * 8;
            const int ac = kk + (lane >> 4) * 8;
#pragma unroll
            for (int ms = 0; ms < 4; ms++) {
                int r = wm + ms * 16 + ar;
                LDSM4(ah[ms][0], ah[ms][1], ah[ms][2], ah[ms][3],
                      smem_u32(&sAhi[r * ASTR + ac]));
                LDSM4(al[ms][0], al[ms][1], al[ms][2], al[ms][3],
                      smem_u32(&sAlo[r * ASTR + ac]));
            }
            const int brow = kk + (lane & 7) + ((lane >> 3) & 1) * 8;
#pragma unroll
            for (int g = 0; g < 2; g++) {
                int c = wn + g * 16 + (lane >> 4) * 8;
                uint32_t r0, r1, r2, r3;
                LDSM4T(r0, r1, r2, r3, smem_u32(&bh_base[brow * BSTR + c]));
                bh[g * 2][0] = r0; bh[g * 2][1] = r1;
                bh[g * 2 + 1][0] = r2; bh[g * 2 + 1][1] = r3;
                LDSM4T(r0, r1, r2, r3, smem_u32(&bl_base[brow * BSTR + c]));
                bl[g * 2][0] = r0; bl[g * 2][1] = r1;
                bl[g * 2 + 1][0] = r2; bl[g * 2 + 1][1] = r3;
            }
#pragma unroll
            for (int ms = 0; ms < 4; ms++)
#pragma unroll
                for (int ns = 0; ns < 4; ns++) {
                    mma_bf16(acc[ms][ns], ah[ms], bh[ns]);
                    mma_bf16(acc[ms][ns], ah[ms], bl[ns]);
                    mma_bf16(acc[ms][ns], al[ms], bh[ns]);
                }
        }
    }

#pragma unroll
    for (int ms = 0; ms < 4; ms++) {
#pragma unroll
        for (int ns = 0; ns < 4; ns++) {
            int row = bm + wm + ms * 16 + (lane >> 2);
            int col = bn + wn + ns * 8 + (lane & 3) * 2;
            if (row < M) {
                float2 o = make_float2(acc[ms][ns][0], acc[ms][ns][1]);
                *(float2*)(C + (size_t)row * 256 + col) = o;
            }
            if (row + 8 < M) {
                float2 o = make_float2(acc[ms][ns][2], acc[ms][ns][3]);
                *(float2*)(C + (size_t)(row + 8) * 256 + col) = o;
            }
        }
    }
}

// ---------- warp-per-node fused GAT: scores + softmax + weighted agg ----------
// For node n: loop its CSR edges; per edge gather hs[src], compute attention
// score against hd[n] (loaded once), exp, accumulate p and p*ew*hs in regs;
// write h[n] = acc / (den + 1e-16). No atomics.
__global__ void __launch_bounds__(256)
node_gat_kernel(const int* __restrict__ src, const float* __restrict__ emask,
                const float* __restrict__ hs, const float* __restrict__ hd,
                const float* __restrict__ a, float* __restrict__ h)
{
    int n = (blockIdx.x * blockDim.x + threadIdx.x) >> 5;
    int lane = threadIdx.x & 31;
    if (n >= N_) return;

    const float4* hdp = (const float4*)(hd + (size_t)n * 256) + lane * 2;
    float4 d0 = __ldg(hdp), d1 = __ldg(hdp + 1);
    const float4* ap = (const float4*)a + lane * 2;
    float4 a0 = __ldg(ap), a1v = __ldg(ap + 1);

    float acc[8];
#pragma unroll
    for (int i = 0; i < 8; i++) acc[i] = 0.0f;
    float den = 0.0f;

    int beg = __ldg(&g_rowptr[n]);
    int end = __ldg(&g_cursor[n]);

    for (int i = beg; i < end; i++) {
        int e = __ldg(&g_eid[i]);
        int s = __ldg(&src[e]);
        float em = __ldg(&emask[e]);
        const float4* hsp = (const float4*)(hs + (size_t)s * 256) + lane * 2;
        float4 s0 = __ldg(hsp), s1 = __ldg(hsp + 1);

        float v, part = 0.0f;
        v = s0.x + d0.x; v = v > 0.f ? v : 0.2f * v; part = fmaf(a0.x, v, part);
        v = s0.y + d0.y; v = v > 0.f ? v : 0.2f * v; part = fmaf(a0.y, v, part);
        v = s0.z + d0.z; v = v > 0.f ? v : 0.2f * v; part = fmaf(a0.z, v, part);
        v = s0.w + d0.w; v = v > 0.f ? v : 0.2f * v; part = fmaf(a0.w, v, part);
        v = s1.x + d1.x; v = v > 0.f ? v : 0.2f * v; part = fmaf(a1v.x, v, part);
        v = s1.y + d1.y; v = v > 0.f ? v : 0.2f * v; part = fmaf(a1v.y, v, part);
        v = s1.z + d1.z; v = v > 0.f ? v : 0.2f * v; part = fmaf(a1v.z, v, part);
        v = s1.w + d1.w; v = v > 0.f ? v : 0.2f * v; part = fmaf(a1v.w, v, part);

        // segmented reduce within each 8-lane group (one head per group)
        part += __shfl_xor_sync(0xffffffffu, part, 1);
        part += __shfl_xor_sync(0xffffffffu, part, 2);
        part += __shfl_xor_sync(0xffffffffu, part, 4);

        float p = expf(part);     // this lane's head score
        den += p;
        float w = p * em;
        acc[0] = fmaf(w, s0.x, acc[0]); acc[1] = fmaf(w, s0.y, acc[1]);
        acc[2] = fmaf(w, s0.z, acc[2]); acc[3] = fmaf(w, s0.w, acc[3]);
        acc[4] = fmaf(w, s1.x, acc[4]); acc[5] = fmaf(w, s1.y, acc[5]);
        acc[6] = fmaf(w, s1.z, acc[6]); acc[7] = fmaf(w, s1.w, acc[7]);
    }

    float inv = 1.0f / (den + 1e-16f);
    float* op = h + (size_t)n * 256 + lane * 8;
    float4 o0 = make_float4(acc[0] * inv, acc[1] * inv, acc[2] * inv, acc[3] * inv);
    float4 o1 = make_float4(acc[4] * inv, acc[5] * inv, acc[6] * inv, acc[7] * inv);
    *(float4*)op = o0;
    *(float4*)(op + 4) = o1;
}

// ---------------- MMA pool: scores -> softmax -> S^T @ X ---------------------
#define XSTR 264
#define WSTR 72
#define POOL_SMEM (2 * 128 * XSTR * 2 + 2 * 256 * WSTR * 2)

__global__ void __launch_bounds__(256)
pool_mma(const float* __restrict__ X, const float* __restrict__ Wa)
{
    extern __shared__ __align__(16) char smem[];
    unsigned short* Xh = (unsigned short*)smem;
    unsigned short* Xl = Xh + 128 * XSTR;
    unsigned short* Wh = Xl + 128 * XSTR;
    unsigned short* Wl = Wh + 256 * WSTR;
    unsigned short* Sh = Wh;
    unsigned short* Sl = Wl;

    const int tid = threadIdx.x;
    const int lane = tid & 31;
    const int warp = tid >> 5;
    const int row0 = blockIdx.x * 128;

#pragma unroll
    for (int j = 0; j < 32; j++) {
        int idx = tid + j * 256;
        int r = idx >> 6;
        int c4 = (idx & 63) << 2;
        int grow = row0 + r;
        float4 v = make_float4(0.f, 0.f, 0.f, 0.f);
        if (grow < N_) v = *(const float4*)(X + (size_t)grow * 256 + c4);
        int base = r * XSTR + c4;
        split1(v.x, &Xh[base + 0], &Xl[base + 0]);
        split1(v.y, &Xh[base + 1], &Xl[base + 1]);
        split1(v.z, &Xh[base + 2], &Xl[base + 2]);
        split1(v.w, &Xh[base + 3], &Xl[base + 3]);
    }
#pragma unroll
    for (int j = 0; j < 16; j++) {
        int idx = tid + j * 256;
        int r = idx >> 4;
        int c4 = (idx & 15) << 2;
        float4 v = *(const float4*)(Wa + (size_t)r * 64 + c4);
        int base = r * WSTR + c4;
        split1(v.x, &Wh[base + 0], &Wl[base + 0]);
        split1(v.y, &Wh[base + 1], &Wl[base + 1]);
        split1(v.z, &Wh[base + 2], &Wl[base + 2]);
        split1(v.w, &Wh[base + 3], &Wl[base + 3]);
    }
    __syncthreads();

    float sc[8][4];
#pragma unroll
    for (int i = 0; i < 8; i++)
#pragma unroll
        for (int r = 0; r < 4; r++) sc[i][r] = 0.0f;

    const int arow = (lane & 7) + ((lane >> 3) & 1) * 8;
#pragma unroll 1
    for (int k = 0; k < 256; k += 16) {
        uint32_t ah[4], al[4];
        int rbase = (warp * 16 + arow) * XSTR + k + (lane >> 4) * 8;
        LDSM4(ah[0], ah[1], ah[2], ah[3], smem_u32(&Xh[rbase]));
        LDSM4(al[0], al[1], al[2], al[3], smem_u32(&Xl[rbase]));
        uint32_t bh[8][2], bl[8][2];
        int brow = k + (lane & 7) + ((lane >> 3) & 1) * 8;
#pragma unroll
        for (int g = 0; g < 4; g++) {
            int c = g * 16 + (lane >> 4) * 8;
            uint32_t r0, r1, r2, r3;
            LDSM4T(r0, r1, r2, r3, smem_u32(&Wh[brow * WSTR + c]));
            bh[g * 2][0] = r0; bh[g * 2][1] = r1;
            bh[g * 2 + 1][0] = r2; bh[g * 2 + 1][1] = r3;
            LDSM4T(r0, r1, r2, r3, smem_u32(&Wl[brow * WSTR + c]));
            bl[g * 2][0] = r0; bl[g * 2][1] = r1;
            bl[g * 2 + 1][0] = r2; bl[g * 2 + 1][1] = r3;
        }
#pragma unroll
        for (int ns = 0; ns < 8; ns++) {
            mma_bf16(sc[ns], ah, bh[ns]);
            mma_bf16(sc[ns], ah, bl[ns]);
            mma_bf16(sc[ns], al, bh[ns]);
        }
    }

    float mA = -1e30f, mB = -1e30f;
#pragma unroll
    for (int ns = 0; ns < 8; ns++) {
        mA = fmaxf(mA, fmaxf(sc[ns][0], sc[ns][1]));
        mB = fmaxf(mB, fmaxf(sc[ns][2], sc[ns][3]));
    }
    mA = fmaxf(mA, __shfl_xor_sync(0xffffffffu, mA, 1));
    mA = fmaxf(mA, __shfl_xor_sync(0xffffffffu, mA, 2));
    mB = fmaxf(mB, __shfl_xor_sync(0xffffffffu, mB, 1));
    mB = fmaxf(mB, __shfl_xor_sync(0xffffffffu, mB, 2));
    float sumA = 0.0f, sumB = 0.0f;
#pragma unroll
    for (int ns = 0; ns < 8; ns++) {
        sc[ns][0] = expf(sc[ns][0] - mA); sc[ns][1] = expf(sc[ns][1] - mA);
        sc[ns][2] = expf(sc[ns][2] - mB); sc[ns][3] = expf(sc[ns][3] - mB);
        sumA += sc[ns][0] + sc[ns][1];
        sumB += sc[ns][2] + sc[ns][3];
    }
    sumA += __shfl_xor_sync(0xffffffffu, sumA, 1);
    sumA += __shfl_xor_sync(0xffffffffu, sumA, 2);
    sumB += __shfl_xor_sync(0xffffffffu, sumB, 1);
    sumB += __shfl_xor_sync(0xffffffffu, sumB, 2);
    float invA = 1.0f / sumA, invB = 1.0f / sumB;

    __syncthreads();

    {
        int rA = warp * 16 + (lane >> 2);
        int rB = rA + 8;
        int colb = (lane & 3) * 2;
#pragma unroll
        for (int ns = 0; ns < 8; ns++) {
            int col = ns * 8 + colb;
            float a0 = sc[ns][0] * invA, a1 = sc[ns][1] * invA;
            float b0 = sc[ns][2] * invB, b1 = sc[ns][3] * invB;
            *(uint32_t*)&Sh[rA * WSTR + col] = pack_bf2(a0, a1);
            *(uint32_t*)&Sl[rA * WSTR + col] = pack_bf2_lo(a0, a1);
            *(uint32_t*)&Sh[rB * WSTR + col] = pack_bf2(b0, b1);
            *(uint32_t*)&Sl[rB * WSTR + col] = pack_bf2_lo(b0, b1);
        }
    }
    __syncthreads();

    float pc[4][4][4];
#pragma unroll
    for (int i = 0; i < 4; i++)
#pragma unroll
        for (int j = 0; j < 4; j++)
#pragma unroll
            for (int r = 0; r < 4; r++) pc[i][j][r] = 0.0f;

    const int nw = warp * 32;
#pragma unroll 1
    for (int kk = 0; kk < 128; kk += 16) {
        uint32_t sah[4][4], sal[4][4];
        int srow = kk + ((lane >> 4) & 1) * 8 + (lane & 7);
        int scoff = ((lane >> 3) & 1) * 8;
#pragma unroll
        for (int mt = 0; mt < 4; mt++) {
            int sc2 = mt * 16 + scoff;
            LDSM4T(sah[mt][0], sah[mt][1], sah[mt][2], sah[mt][3],
                   smem_u32(&Sh[srow * WSTR + sc2]));
            LDSM4T(sal[mt][0], sal[mt][1], sal[mt][2], sal[mt][3],
                   smem_u32(&Sl[srow * WSTR + sc2]));
        }
        uint32_t xbh[4][2], xbl[4][2];
        int brow = kk + (lane & 7) + ((lane >> 3) & 1) * 8;
#pragma unroll
        for (int g = 0; g < 2; g++) {
            int c = nw + g * 16 + (lane >> 4) * 8;
            uint32_t r0, r1, r2, r3;
            LDSM4T(r0, r1, r2, r3, smem_u32(&Xh[brow * XSTR + c]));
            xbh[g * 2][0] = r0; xbh[g * 2][1] = r1;
            xbh[g * 2 + 1][0] = r2; xbh[g * 2 + 1][1] = r3;
            LDSM4T(r0, r1, r2, r3, smem_u32(&Xl[brow * XSTR + c]));
            xbl[g * 2][0] = r0; xbl[g * 2][1] = r1;
            xbl[g * 2 + 1][0] = r2; xbl[g * 2 + 1][1] = r3;
        }
#pragma unroll
        for (int mt = 0; mt < 4; mt++)
#pragma unroll
            for (int ns = 0; ns < 4; ns++) {
                mma_bf16(pc[mt][ns], sah[mt], xbh[ns]);
                mma_bf16(pc[mt][ns], sah[mt], xbl[ns]);
                mma_bf16(pc[mt][ns], sal[mt], xbh[ns]);
            }
    }

#pragma unroll
    for (int mt = 0; mt < 4; mt++)
#pragma unroll
        for (int ns = 0; ns < 4; ns++) {
            int kidx = mt * 16 + (lane >> 2);
            int col = nw + ns * 8 + (lane & 3) * 2;
            redAddV2(&g_pool[(size_t)kidx * 256 + col], pc[mt][ns][0], pc[mt][ns][1]);
            redAddV2(&g_pool[(size_t)(kidx + 8) * 256 + col], pc[mt][ns][2], pc[mt][ns][3]);
        }
}

// ---------------- edge_attr means over all T ---------------------------------
__global__ void edge_sum_kernel(const float* __restrict__ ea)
{
    int t = blockIdx.y;
    const float* p = ea + (size_t)t * E_;
    float s = 0.0f;
    for (int i = blockIdx.x * blockDim.x + threadIdx.x; i < E_; i += gridDim.x * blockDim.x)
        s += p[i];
#pragma unroll
    for (int o = 16; o; o >>= 1) s += __shfl_xor_sync(0xffffffffu, s, o);
    __shared__ float red[8];
    int lane = threadIdx.x & 31, w = threadIdx.x >> 5;
    if (lane == 0) red[w] = s;
    __syncthreads();
    if (threadIdx.x == 0) {
        float bs = 0.0f;
        for (int i = 0; i < (int)(blockDim.x >> 5); i++) bs += red[i];
        atomicAdd(&g_esum[t], bs);
    }
}

// ---------------- final classifier -------------------------------------------
__global__ void final_kernel(const float* __restrict__ Wcls, const float* __restrict__ bcls,
                             float* __restrict__ out)
{
    int k = blockIdx.x;
    int lane = threadIdx.x;
    float s = 0.0f;
    for (int d = lane; d < 256; d += 32) s += g_pool[(size_t)k * 256 + d] * Wcls[d];
#pragma unroll
    for (int o = 16; o; o >>= 1) s += __shfl_xor_sync(0xffffffffu, s, o);
    if (lane == 0) {
        float extra = 0.0f;
#pragma unroll
        for (int t = 0; t < T_; t++) extra += (g_esum[t] * (1.0f / E_)) * Wcls[256 + t];
        float z = s + extra + bcls[0];
        out[k] = 1.0f / (1.0f + expf(-z));
    }
}

// ---------------- launch -------------------------------------------------------
extern "C" void kernel_launch(void* const* d_in, const int* in_sizes, int n_in,
                              void* d_out, int out_size)
{
    const float* x_pkg = (const float*)d_in[0];
    const float* x_dst = (const float*)d_in[1];
    const int*   eidx  = (const int*)d_in[2];
    const float* eattr = (const float*)d_in[3];
    const float* nmask = (const float*)d_in[4];
    const float* emask = (const float*)d_in[5];
    const float* W1s   = (const float*)d_in[6];
    const float* W1d   = (const float*)d_in[7];
    const float* a1    = (const float*)d_in[8];
    const float* W2s   = (const float*)d_in[9];
    const float* W2d   = (const float*)d_in[10];
    const float* a2    = (const float*)d_in[11];
    const float* Was   = (const float*)d_in[12];
    const float* Wcl   = (const float*)d_in[13];
    const float* bcl   = (const float*)d_in[14];
    float* out = (float*)d_out;

    const int tsel = T_ - 1;
    const int* src5 = eidx + (size_t)tsel * 2 * E_;
    const int* dst5 = src5 + E_;
    const float* x_dst5 = x_dst + (size_t)tsel * N_ * D_;
    const float* W1s5 = W1s + (size_t)tsel * D_ * 256;
    const float* W1d5 = W1d + (size_t)tsel * D_ * 256;
    const float* a1_5 = a1 + (size_t)tsel * 256;
    const float* W2s5 = W2s + (size_t)tsel * D_ * 256;
    const float* W2d5 = W2d + (size_t)tsel * D_ * 256;
    const float* a2_5 = a2 + (size_t)tsel * 256;

    float *hs1, *hd1, *hs2, *hd2, *h1, *h2;
    unsigned short *whi, *wlo;
    cudaGetSymbolAddress((void**)&hs1, g_hs1);
    cudaGetSymbolAddress((void**)&hd1, g_hd1);
    cudaGetSymbolAddress((void**)&hs2, g_hs2);
    cudaGetSymbolAddress((void**)&hd2, g_hd2);
    cudaGetSymbolAddress((void**)&h1,  g_h1);
    cudaGetSymbolAddress((void**)&h2,  g_h2);
    cudaGetSymbolAddress((void**)&whi, g_Whi);
    cudaGetSymbolAddress((void**)&wlo, g_Wlo);

    cudaFuncSetAttribute(pool_mma, cudaFuncAttributeMaxDynamicSharedMemorySize, POOL_SMEM);
    cudaFuncSetAttribute(gemm_mma<0>, cudaFuncAttributeMaxDynamicSharedMemorySize, GEMM_SMEM);
    cudaFuncSetAttribute(gemm_mma<1>, cudaFuncAttributeMaxDynamicSharedMemorySize, GEMM_SMEM);

    dim3 ggrid(391, 2);
    const int egrid = (E_ + 255) / 256;
    const int ngrid = (N_ * 32 + 255) / 256;   // warp per node

    init_kernel<<<512, 256>>>();
    split_w_kernel<<<dim3(256, 4), 256>>>(W1s5, W1d5, W2s5, W2d5);

    // CSR build (shared by both layers)
    hist_kernel<<<egrid, 256>>>(dst5);
    scanA_kernel<<<SCAN_B, 256>>>();
    scanB_kernel<<<1, 256>>>();
    scanC_kernel<<<SCAN_B, 256>>>();
    scatter_kernel<<<egrid, 256>>>(dst5);

    // projections (tensor cores)
    gemm_mma<0><<<ggrid, 256, GEMM_SMEM>>>(x_pkg,  nmask, whi + 0 * 65536, wlo + 0 * 65536, hs1, N_);
    gemm_mma<0><<<ggrid, 256, GEMM_SMEM>>>(x_dst5, nmask, whi + 1 * 65536, wlo + 1 * 65536, hd1, N_);
    gemm_mma<1><<<ggrid, 256, GEMM_SMEM>>>(x_pkg,  nullptr, whi + 2 * 65536, wlo + 2 * 65536, hs2, N_);

    // layer 1: fused warp-per-node GAT (writes normalized h1)
    node_gat_kernel<<<ngrid, 256>>>(src5, emask, hs1, hd1, a1_5, h1);

    // layer-2 dst projection (relu on h1 in staging)
    gemm_mma<1><<<ggrid, 256, GEMM_SMEM>>>(h1, nullptr, whi + 3 * 65536, wlo + 3 * 65536, hd2, N_);

    // layer 2: fused node GAT (writes normalized h2)
    node_gat_kernel<<<ngrid, 256>>>(src5, emask, hs2, hd2, a2_5, h2);

    // epilogue
    edge_sum_kernel<<<dim3(32, T_), 256>>>(eattr);
    pool_mma<<<391, 256, POOL_SMEM>>>(h2, Was);
    final_kernel<<<K_, 32>>>(Wcl, bcl, out);
}